// round 2
// baseline (speedup 1.0000x reference)
#include <cuda_runtime.h>
#include <cstddef>

#define NPTS 120000
#define CDIM 128
#define NW   12000
#define SQL  16
#define SKL  64
#define NH   8
#define HD   16
#define FFD  512
#define TQ   (NW*SQL)   /* 192000 */
#define TK   (NW*SKL)   /* 768000 */

// ---------------- single static arena with aliased sub-buffers ----------------
// live:   h | qf | kt | Q | K | V           (peak 1.44 GB, < 2 GB reloc limit)
// alias:  ao<-qf, ob/cnt/y<-kt, sums<-h, h2<-V, mid<-K
#define O_H   ((size_t)0)
#define O_QF  (O_H  + (size_t)NPTS*CDIM)
#define O_KT  (O_QF + (size_t)TQ*CDIM)
#define O_Q   (O_KT + (size_t)TK*CDIM)
#define O_K   (O_Q  + (size_t)TQ*CDIM)
#define O_V   (O_K  + (size_t)TK*CDIM)
#define ARENA_FLOATS (O_V + (size_t)TK*CDIM)   /* 359,424,000 floats = 1.438 GB */

#define O_AO   O_QF
#define O_OB   O_KT
#define O_CNT  (O_KT + (size_t)TQ*CDIM)
#define O_Y    (O_CNT + (size_t)NPTS + 64)
#define O_SUMS O_H
#define O_H2   O_V
#define O_MID  O_K

__device__ float g_arena[ARENA_FLOATS];

// ---------------- LayerNorm: one warp per 128-wide row ----------------
__global__ void ln_kernel(const float* __restrict__ x, const float* __restrict__ g,
                          const float* __restrict__ b, float* __restrict__ out, int rows)
{
    int gid  = blockIdx.x * blockDim.x + threadIdx.x;
    int row  = gid >> 5;
    int lane = gid & 31;
    if (row >= rows) return;
    float4 v = *((const float4*)(x + (size_t)row * CDIM) + lane);
    float s  = v.x + v.y + v.z + v.w;
    float sq = v.x*v.x + v.y*v.y + v.z*v.z + v.w*v.w;
    #pragma unroll
    for (int o = 16; o > 0; o >>= 1) {
        s  += __shfl_xor_sync(0xffffffffu, s,  o);
        sq += __shfl_xor_sync(0xffffffffu, sq, o);
    }
    float m   = s * (1.0f / CDIM);
    float var = sq * (1.0f / CDIM) - m * m;
    float rs  = rsqrtf(var + 1e-5f);
    float4 gg = ((const float4*)g)[lane];
    float4 bb = ((const float4*)b)[lane];
    float4 o4;
    o4.x = (v.x - m) * rs * gg.x + bb.x;
    o4.y = (v.y - m) * rs * gg.y + bb.y;
    o4.z = (v.z - m) * rs * gg.z + bb.z;
    o4.w = (v.w - m) * rs * gg.w + bb.w;
    *((float4*)(out + (size_t)row * CDIM) + lane) = o4;
}

// ---------------- generic tiled fp32 GEMM ----------------
// C = A[M,K] @ B[K,Nc] (+bias)(relu)(+gather h[idx])(+residual)
// POSA: A is pos[M,6]; effective A = relu(pos @ w1 + b1) computed in the tile load
// BM=128, BN=64, BK=16, 128 threads, 8x8 per thread
template<bool RELU, bool GATHER, bool RES, bool POSA>
__global__ void __launch_bounds__(128) gemm_k(
    const float* __restrict__ A, const float* __restrict__ B,
    const float* __restrict__ bias, float* __restrict__ Cout,
    int M, int K, int Nc,
    const int* __restrict__ gidx, const float* __restrict__ gsrc,
    const float* __restrict__ res,
    const float* __restrict__ pw1, const float* __restrict__ pb1)
{
    __shared__ float As[16][132];
    __shared__ float Bs[16][64];
    __shared__ float Ws[6][16];
    __shared__ float bs[16];
    const int tid = threadIdx.x;
    const int tx = tid & 7;    // n dir
    const int ty = tid >> 3;   // m dir
    const int mBase = blockIdx.x * 128;
    const int nBase = blockIdx.y * 64;

    float preg[6];
    if (POSA) {
        // M divisible by 128 on all POSA launches
        const float* pp = A + (size_t)(mBase + tid) * 6;
        #pragma unroll
        for (int i = 0; i < 6; i++) preg[i] = pp[i];
    }

    float acc[8][8];
    #pragma unroll
    for (int r = 0; r < 8; r++)
        #pragma unroll
        for (int c = 0; c < 8; c++) acc[r][c] = 0.f;

    for (int k0 = 0; k0 < K; k0 += 16) {
        if (POSA) {
            if (tid < 24) {
                int r = tid >> 2, c4 = (tid & 3) * 4;
                *(float4*)(&Ws[r][c4]) = *(const float4*)(pw1 + r * CDIM + k0 + c4);
            }
            if (tid < 4) *(float4*)(&bs[tid * 4]) = *(const float4*)(pb1 + k0 + tid * 4);
            __syncthreads();
            #pragma unroll
            for (int cc = 0; cc < 16; cc++) {
                float v = bs[cc];
                #pragma unroll
                for (int i = 0; i < 6; i++) v = fmaf(preg[i], Ws[i][cc], v);
                As[cc][tid] = fmaxf(v, 0.f);
            }
        } else {
            #pragma unroll
            for (int i = 0; i < 4; i++) {
                int f4 = i * 128 + tid;
                int r = f4 >> 2;
                int cc = (f4 & 3) * 4;
                float4 v = make_float4(0.f, 0.f, 0.f, 0.f);
                int grow = mBase + r;
                if (grow < M)
                    v = *(const float4*)(A + (size_t)grow * K + (k0 + cc));
                As[cc + 0][r] = v.x; As[cc + 1][r] = v.y;
                As[cc + 2][r] = v.z; As[cc + 3][r] = v.w;
            }
        }
        #pragma unroll
        for (int i = 0; i < 2; i++) {
            int f4 = i * 128 + tid;
            int r = f4 >> 4;
            int cc = (f4 & 15) * 4;
            *(float4*)(&Bs[r][cc]) =
                *(const float4*)(B + (size_t)(k0 + r) * Nc + (nBase + cc));
        }
        __syncthreads();
        #pragma unroll
        for (int kk = 0; kk < 16; kk++) {
            float a[8], bb[8];
            *(float4*)(a)     = *(const float4*)(&As[kk][ty * 8]);
            *(float4*)(a + 4) = *(const float4*)(&As[kk][ty * 8 + 4]);
            *(float4*)(bb)     = *(const float4*)(&Bs[kk][tx * 8]);
            *(float4*)(bb + 4) = *(const float4*)(&Bs[kk][tx * 8 + 4]);
            #pragma unroll
            for (int r = 0; r < 8; r++)
                #pragma unroll
                for (int c = 0; c < 8; c++)
                    acc[r][c] = fmaf(a[r], bb[c], acc[r][c]);
        }
        __syncthreads();
    }

    const int n0 = nBase + tx * 8;
    float bi[8];
    *(float4*)(bi)     = *(const float4*)(bias + n0);
    *(float4*)(bi + 4) = *(const float4*)(bias + n0 + 4);
    #pragma unroll
    for (int r = 0; r < 8; r++) {
        int grow = mBase + ty * 8 + r;
        if (grow >= M) continue;
        float o[8];
        #pragma unroll
        for (int c = 0; c < 8; c++) {
            float v = acc[r][c] + bi[c];
            if (RELU) v = fmaxf(v, 0.f);
            o[c] = v;
        }
        if (GATHER) {
            const float* gp = gsrc + (size_t)gidx[grow] * CDIM + n0;
            #pragma unroll
            for (int c = 0; c < 8; c++) o[c] += gp[c];
        }
        if (RES) {
            const float* rp = res + (size_t)grow * Nc + n0;
            #pragma unroll
            for (int c = 0; c < 8; c++) o[c] += rp[c];
        }
        float* op = Cout + (size_t)grow * Nc + n0;
        *(float4*)(op)     = *(float4*)(o);
        *(float4*)(op + 4) = *(float4*)(o + 4);
    }
}

// ---------------- attention: one block per window, thread = (q,h) pair ----------------
__global__ void __launch_bounds__(128) attn_kernel(
    const float* __restrict__ Qb, const float* __restrict__ Kb,
    const float* __restrict__ Vb, const int* __restrict__ kmask,
    float* __restrict__ Ao)
{
    __shared__ float sQ[SQL][CDIM];
    __shared__ float sKV[SKL][132];
    __shared__ int   sM[SKL];
    const int w = blockIdx.x;
    const int tid = threadIdx.x;
    const int h = tid & 7;
    const int q = tid >> 3;

    #pragma unroll
    for (int i = 0; i < 4; i++) {
        int f4 = i * 128 + tid;
        int r = f4 >> 5, c = (f4 & 31) * 4;
        *(float4*)(&sQ[r][c]) = *(const float4*)(Qb + (size_t)(w * SQL + r) * CDIM + c);
    }
    #pragma unroll
    for (int i = 0; i < 16; i++) {
        int f4 = i * 128 + tid;
        int r = f4 >> 5, c = (f4 & 31) * 4;
        *(float4*)(&sKV[r][c]) = *(const float4*)(Kb + (size_t)(w * SKL + r) * CDIM + c);
    }
    if (tid < SKL) sM[tid] = kmask[w * SKL + tid];
    __syncthreads();

    float qreg[16];
    #pragma unroll
    for (int j = 0; j < 4; j++)
        *(float4*)(qreg + j * 4) = *(const float4*)(&sQ[q][h * 16 + j * 4]);

    float s[SKL];
    #pragma unroll
    for (int k = 0; k < SKL; k++) {
        float4 v0 = *(const float4*)(&sKV[k][h * 16 + 0]);
        float4 v1 = *(const float4*)(&sKV[k][h * 16 + 4]);
        float4 v2 = *(const float4*)(&sKV[k][h * 16 + 8]);
        float4 v3 = *(const float4*)(&sKV[k][h * 16 + 12]);
        float acc = qreg[0]*v0.x + qreg[1]*v0.y + qreg[2]*v0.z + qreg[3]*v0.w
                  + qreg[4]*v1.x + qreg[5]*v1.y + qreg[6]*v1.z + qreg[7]*v1.w
                  + qreg[8]*v2.x + qreg[9]*v2.y + qreg[10]*v2.z + qreg[11]*v2.w
                  + qreg[12]*v3.x + qreg[13]*v3.y + qreg[14]*v3.z + qreg[15]*v3.w;
        s[k] = sM[k] ? -1e9f : acc * 0.25f;
    }
    float mx = -1e30f;
    #pragma unroll
    for (int k = 0; k < SKL; k++) mx = fmaxf(mx, s[k]);
    float sum = 0.f;
    #pragma unroll
    for (int k = 0; k < SKL; k++) { float e = expf(s[k] - mx); s[k] = e; sum += e; }
    float inv = 1.f / sum;
    #pragma unroll
    for (int k = 0; k < SKL; k++) s[k] *= inv;

    __syncthreads();   // everyone done reading K
    #pragma unroll
    for (int i = 0; i < 16; i++) {
        int f4 = i * 128 + tid;
        int r = f4 >> 5, c = (f4 & 31) * 4;
        *(float4*)(&sKV[r][c]) = *(const float4*)(Vb + (size_t)(w * SKL + r) * CDIM + c);
    }
    __syncthreads();

    float4 o0 = make_float4(0,0,0,0), o1 = o0, o2 = o0, o3 = o0;
    #pragma unroll
    for (int k = 0; k < SKL; k++) {
        float p = s[k];
        float4 v0 = *(const float4*)(&sKV[k][h * 16 + 0]);
        float4 v1 = *(const float4*)(&sKV[k][h * 16 + 4]);
        float4 v2 = *(const float4*)(&sKV[k][h * 16 + 8]);
        float4 v3 = *(const float4*)(&sKV[k][h * 16 + 12]);
        o0.x = fmaf(p, v0.x, o0.x); o0.y = fmaf(p, v0.y, o0.y);
        o0.z = fmaf(p, v0.z, o0.z); o0.w = fmaf(p, v0.w, o0.w);
        o1.x = fmaf(p, v1.x, o1.x); o1.y = fmaf(p, v1.y, o1.y);
        o1.z = fmaf(p, v1.z, o1.z); o1.w = fmaf(p, v1.w, o1.w);
        o2.x = fmaf(p, v2.x, o2.x); o2.y = fmaf(p, v2.y, o2.y);
        o2.z = fmaf(p, v2.z, o2.z); o2.w = fmaf(p, v2.w, o2.w);
        o3.x = fmaf(p, v3.x, o3.x); o3.y = fmaf(p, v3.y, o3.y);
        o3.z = fmaf(p, v3.z, o3.z); o3.w = fmaf(p, v3.w, o3.w);
    }
    float* op = Ao + (size_t)(w * SQL + q) * CDIM + h * 16;
    *(float4*)(op + 0)  = o0;
    *(float4*)(op + 4)  = o1;
    *(float4*)(op + 8)  = o2;
    *(float4*)(op + 12) = o3;
}

// ---------------- scatter-mean support ----------------
__global__ void clear_kernel(float* __restrict__ sums, float* __restrict__ cnt)
{
    int i = blockIdx.x * blockDim.x + threadIdx.x;
    if (i < NPTS * CDIM) sums[i] = 0.f;
    if (i < NPTS) cnt[i] = 0.f;
}

__global__ void scatter_kernel(const int* __restrict__ qind, const int* __restrict__ qmask,
                               const float* __restrict__ ob,
                               float* __restrict__ sums, float* __restrict__ cnt)
{
    int e = blockIdx.x * blockDim.x + threadIdx.x;
    if (e >= TQ * CDIM) return;
    int t = e >> 7, c = e & 127;
    if (qmask[t] == 0) {   // valid query (bit-pattern test: works for int32 or f32 bool)
        int idx = qind[t];
        atomicAdd(&sums[(size_t)idx * CDIM + c], ob[e]);
        if (c == 0) atomicAdd(&cnt[idx], 1.0f);
    }
}

__global__ void resid_kernel(const float* __restrict__ feat, const float* __restrict__ sums,
                             const float* __restrict__ cnt, float* __restrict__ y)
{
    int e = blockIdx.x * blockDim.x + threadIdx.x;
    if (e >= NPTS * CDIM) return;
    int row = e >> 7;
    y[e] = feat[e] + sums[e] / fmaxf(cnt[row], 1.0f);
}

// ---------------- launch ----------------
extern "C" void kernel_launch(void* const* d_in, const int* in_sizes, int n_in,
                              void* d_out, int out_size)
{
    const float *features=nullptr, *q_pos=nullptr, *k_pos=nullptr;
    const float *ln1_g=nullptr, *ln1_b=nullptr, *pw1=nullptr, *pb1=nullptr;
    const float *pw2=nullptr, *pb2=nullptr;
    const float *wq=nullptr,*bq=nullptr,*wk=nullptr,*bk=nullptr,*wv=nullptr,*bv=nullptr,*wo=nullptr,*bo=nullptr;
    const float *ln2_g=nullptr,*ln2_b=nullptr,*fw1=nullptr,*fb1=nullptr,*fw2=nullptr,*fb2=nullptr;
    const int *q_ind=nullptr,*q_mask=nullptr,*k_ind=nullptr,*k_mask=nullptr;

    // relative order of equal-size tensors is identical for both plausible metadata orders
    const float** slots128[11] = {&ln1_g,&ln1_b,&pb1,&pb2,&bq,&bk,&bv,&bo,&ln2_g,&ln2_b,&fb2};
    int c192=0, c768k=0, c16k=0, c64k=0, c128=0;
    for (int i = 0; i < n_in; i++) {
        int s = in_sizes[i];
        const void* p = d_in[i];
        if      (s == NPTS*CDIM)   features = (const float*)p;
        else if (s == NW*SQL*6)    q_pos = (const float*)p;
        else if (s == NW*SKL*6)    k_pos = (const float*)p;
        else if (s == NW*SQL)      { if (c192++ == 0) q_ind = (const int*)p; else q_mask = (const int*)p; }
        else if (s == NW*SKL)      { if (c768k++ == 0) k_ind = (const int*)p; else k_mask = (const int*)p; }
        else if (s == 6*CDIM)      pw1 = (const float*)p;
        else if (s == CDIM*CDIM) {
            const float* f = (const float*)p;
            switch (c16k++) { case 0: pw2=f; break; case 1: wq=f; break; case 2: wk=f; break;
                              case 3: wv=f; break; default: wo=f; break; }
        }
        else if (s == CDIM*FFD)    { if (c64k++ == 0) fw1 = (const float*)p; else fw2 = (const float*)p; }
        else if (s == FFD)         fb1 = (const float*)p;
        else if (s == CDIM)        { if (c128 < 11) *slots128[c128] = (const float*)p; c128++; }
    }

    float* arena = nullptr;
    cudaGetSymbolAddress((void**)&arena, g_arena);
    float* hb   = arena + O_H;
    float* qf   = arena + O_QF;
    float* kt   = arena + O_KT;
    float* Qb   = arena + O_Q;
    float* Kb   = arena + O_K;
    float* Vb   = arena + O_V;
    float* ao   = arena + O_AO;
    float* ob   = arena + O_OB;
    float* cnt  = arena + O_CNT;
    float* yb   = arena + O_Y;
    float* sums = arena + O_SUMS;
    float* h2b  = arena + O_H2;
    float* midb = arena + O_MID;
    float* out  = (float*)d_out;

    // 1. pre-norm
    ln_kernel<<<(NPTS*32 + 255)/256, 256>>>(features, ln1_g, ln1_b, hb, NPTS);
    // 2. fused pos-MLP (l1 in A-load, l2 = GEMM) + gather h[ind]
    gemm_k<true,true,false,true><<<dim3(TQ/128, CDIM/64), 128>>>(q_pos, pw2, pb2, qf, TQ, CDIM, CDIM, q_ind, hb, nullptr, pw1, pb1);
    gemm_k<true,true,false,true><<<dim3(TK/128, CDIM/64), 128>>>(k_pos, pw2, pb2, kt, TK, CDIM, CDIM, k_ind, hb, nullptr, pw1, pb1);
    // 3. Q/K/V projections
    gemm_k<false,false,false,false><<<dim3(TQ/128, CDIM/64), 128>>>(qf, wq, bq, Qb, TQ, CDIM, CDIM, nullptr, nullptr, nullptr, nullptr, nullptr);
    gemm_k<false,false,false,false><<<dim3(TK/128, CDIM/64), 128>>>(kt, wk, bk, Kb, TK, CDIM, CDIM, nullptr, nullptr, nullptr, nullptr, nullptr);
    gemm_k<false,false,false,false><<<dim3(TK/128, CDIM/64), 128>>>(kt, wv, bv, Vb, TK, CDIM, CDIM, nullptr, nullptr, nullptr, nullptr, nullptr);
    // 4. windowed attention (writes ao, aliased onto qf)
    attn_kernel<<<NW, 128>>>(Qb, Kb, Vb, k_mask, ao);
    // 5. output projection (writes ob, aliased onto kt)
    gemm_k<false,false,false,false><<<dim3(TQ/128, CDIM/64), 128>>>(ao, wo, bo, ob, TQ, CDIM, CDIM, nullptr, nullptr, nullptr, nullptr, nullptr);
    // 6. masked scatter-mean + residual (sums aliased onto h)
    clear_kernel<<<(NPTS*CDIM + 255)/256, 256>>>(sums, cnt);
    scatter_kernel<<<(TQ*CDIM + 255)/256, 256>>>(q_ind, q_mask, ob, sums, cnt);
    resid_kernel<<<(NPTS*CDIM + 255)/256, 256>>>(features, sums, cnt, yb);
    // 7. FFN with pre-norm + residual (h2 on V, mid on K)
    ln_kernel<<<(NPTS*32 + 255)/256, 256>>>(yb, ln2_g, ln2_b, h2b, NPTS);
    gemm_k<true,false,false,false><<<dim3((NPTS + 127)/128, FFD/64), 128>>>(h2b, fw1, fb1, midb, NPTS, CDIM, FFD, nullptr, nullptr, nullptr, nullptr, nullptr);
    gemm_k<false,false,true,false><<<dim3((NPTS + 127)/128, CDIM/64), 128>>>(midb, fw2, fb2, out, NPTS, FFD, CDIM, nullptr, nullptr, yb, nullptr, nullptr);
}

// round 4
// speedup vs baseline: 1.8136x; 1.8136x over previous
#include <cuda_runtime.h>
#include <cstddef>
#include <cstdint>

#define NPTS 120000
#define CDIM 128
#define NW   12000
#define SQL  16
#define SKL  64
#define FFD  512
#define TQ   (NW*SQL)   /* 192000 */
#define TK   (NW*SKL)   /* 768000 */

// ---------------- single static arena with aliased sub-buffers ----------------
#define O_H   ((size_t)0)
#define O_QF  (O_H  + (size_t)NPTS*CDIM)
#define O_KT  (O_QF + (size_t)TQ*CDIM)
#define O_Q   (O_KT + (size_t)TK*CDIM)
#define O_K   (O_Q  + (size_t)TQ*CDIM)
#define O_V   (O_K  + (size_t)TK*CDIM)
#define ARENA_FLOATS (O_V + (size_t)TK*CDIM)

#define O_AO   O_QF
#define O_OB   O_KT
#define O_CNT  (O_KT + (size_t)TQ*CDIM)
#define O_Y    (O_CNT + (size_t)NPTS + 64)
#define O_SUMS O_H
#define O_H2   O_V
#define O_MID  O_K

__device__ float g_arena[ARENA_FLOATS];

// ---------------- PTX helpers ----------------
__device__ __forceinline__ uint32_t pk_bf2(float lo, float hi) {
    uint32_t r;
    asm("cvt.rn.bf16x2.f32 %0, %1, %2;" : "=r"(r) : "f"(hi), "f"(lo));
    return r;
}
__device__ __forceinline__ void ldsm4(uint32_t* r, uint32_t addr) {
    asm volatile("ldmatrix.sync.aligned.m8n8.x4.shared.b16 {%0,%1,%2,%3}, [%4];"
        : "=r"(r[0]), "=r"(r[1]), "=r"(r[2]), "=r"(r[3]) : "r"(addr));
}
__device__ __forceinline__ void ldsm4t(uint32_t* r, uint32_t addr) {
    asm volatile("ldmatrix.sync.aligned.m8n8.x4.trans.shared.b16 {%0,%1,%2,%3}, [%4];"
        : "=r"(r[0]), "=r"(r[1]), "=r"(r[2]), "=r"(r[3]) : "r"(addr));
}
__device__ __forceinline__ void mma16816(float* d, const uint32_t* a, const uint32_t* b) {
    asm volatile("mma.sync.aligned.m16n8k16.row.col.f32.bf16.bf16.f32 "
        "{%0,%1,%2,%3}, {%4,%5,%6,%7}, {%8,%9}, {%0,%1,%2,%3};"
        : "+f"(d[0]), "+f"(d[1]), "+f"(d[2]), "+f"(d[3])
        : "r"(a[0]), "r"(a[1]), "r"(a[2]), "r"(a[3]), "r"(b[0]), "r"(b[1]));
}

// ---------------- LayerNorm ----------------
__global__ void ln_kernel(const float* __restrict__ x, const float* __restrict__ g,
                          const float* __restrict__ b, float* __restrict__ out, int rows)
{
    int gid  = blockIdx.x * blockDim.x + threadIdx.x;
    int row  = gid >> 5;
    int lane = gid & 31;
    if (row >= rows) return;
    float4 v = *((const float4*)(x + (size_t)row * CDIM) + lane);
    float s  = v.x + v.y + v.z + v.w;
    float sq = v.x*v.x + v.y*v.y + v.z*v.z + v.w*v.w;
    #pragma unroll
    for (int o = 16; o > 0; o >>= 1) {
        s  += __shfl_xor_sync(0xffffffffu, s,  o);
        sq += __shfl_xor_sync(0xffffffffu, sq, o);
    }
    float m   = s * (1.0f / CDIM);
    float var = sq * (1.0f / CDIM) - m * m;
    float rs  = rsqrtf(var + 1e-5f);
    float4 gg = ((const float4*)g)[lane];
    float4 bb = ((const float4*)b)[lane];
    float4 o4;
    o4.x = (v.x - m) * rs * gg.x + bb.x;
    o4.y = (v.y - m) * rs * gg.y + bb.y;
    o4.z = (v.z - m) * rs * gg.z + bb.z;
    o4.w = (v.w - m) * rs * gg.w + bb.w;
    *((float4*)(out + (size_t)row * CDIM) + lane) = o4;
}

// ---------------- bf16 HMMA GEMM ----------------
// C = A[M,K] @ B[K,Nc]  (+bias)(relu)(+gather h[idx])(+residual)
// POSA: A replaced by relu(pos@w1+b1) computed in tile build.
// BM=128, BN=128, BK=32, 256 threads (8 warps: 2m x 4n, warp tile 64x32)
#define LDA_S 40    /* bf16 elems per As row (32 + 8 pad) */
#define LDB_S 136   /* bf16 elems per Bs row (128 + 8 pad) */

template<bool RELU, bool GATHER, bool RES, bool POSA>
__global__ void __launch_bounds__(256) gemm_mma(
    const float* __restrict__ A, const float* __restrict__ B,
    const float* __restrict__ bias, float* __restrict__ Cout,
    int M, int K, int Nc,
    const int* __restrict__ gidx, const float* __restrict__ gsrc,
    const float* __restrict__ res,
    const float* __restrict__ pw1, const float* __restrict__ pb1)
{
    __shared__ uint32_t As_u[128 * (LDA_S/2)];      // 128 x 40 bf16
    __shared__ uint32_t Bs_u[32 * (LDB_S/2)];       // 32 x 136 bf16
    __shared__ float    Wall[6*CDIM + CDIM];        // POSA: w1 (6x128) + b1 (128)

    const int tid  = threadIdx.x;
    const int lane = tid & 31;
    const int wid  = tid >> 5;
    const int wm   = wid & 1;       // 0..1 (m)
    const int wn   = wid >> 1;      // 0..3 (n)
    const int mBase = blockIdx.x * 128;
    const int nBase = blockIdx.y * 128;

    float preg[6];
    if (POSA) {
        const float* pp = A + (size_t)(mBase + (tid >> 1)) * 6;
        #pragma unroll
        for (int i = 0; i < 6; i++) preg[i] = pp[i];
        if (tid < 192) ((float4*)Wall)[tid] = ((const float4*)pw1)[tid];
        if (tid < 32)  ((float4*)(Wall + 6*CDIM))[tid] = ((const float4*)pb1)[tid];
        __syncthreads();
    }

    uint32_t asBase = (uint32_t)__cvta_generic_to_shared(As_u);
    uint32_t bsBase = (uint32_t)__cvta_generic_to_shared(Bs_u);

    float acc[4][4][4];
    #pragma unroll
    for (int mt = 0; mt < 4; mt++)
        #pragma unroll
        for (int nt = 0; nt < 4; nt++)
            #pragma unroll
            for (int i = 0; i < 4; i++) acc[mt][nt][i] = 0.f;

    // prefetch registers
    float4 ra[4], rb[4];
    auto loadA = [&](int k0) {
        #pragma unroll
        for (int i = 0; i < 4; i++) {
            int f = i * 256 + tid;
            int r = f >> 3, c4 = (f & 7) << 2;
            int grow = mBase + r;
            ra[i] = (grow < M) ? *(const float4*)(A + (size_t)grow * K + k0 + c4)
                               : make_float4(0.f, 0.f, 0.f, 0.f);
        }
    };
    auto loadB = [&](int k0) {
        #pragma unroll
        for (int i = 0; i < 4; i++) {
            int f = i * 256 + tid;
            int r = f >> 5, c4 = (f & 31) << 2;
            rb[i] = *(const float4*)(B + (size_t)(k0 + r) * Nc + nBase + c4);
        }
    };

    if (!POSA) loadA(0);
    loadB(0);

    for (int k0 = 0; k0 < K; k0 += 32) {
        // ---- store tiles to smem (convert to bf16) ----
        if (POSA) {
            const int row = tid >> 1;
            const int cb  = (tid & 1) * 16;
            #pragma unroll
            for (int cc = 0; cc < 16; cc += 2) {
                int kc = k0 + cb + cc;
                float v0 = Wall[6*CDIM + kc];
                float v1 = Wall[6*CDIM + kc + 1];
                #pragma unroll
                for (int i = 0; i < 6; i++) {
                    v0 = fmaf(preg[i], Wall[i*CDIM + kc],     v0);
                    v1 = fmaf(preg[i], Wall[i*CDIM + kc + 1], v1);
                }
                v0 = fmaxf(v0, 0.f); v1 = fmaxf(v1, 0.f);
                As_u[row * (LDA_S/2) + ((cb + cc) >> 1)] = pk_bf2(v0, v1);
            }
        } else {
            #pragma unroll
            for (int i = 0; i < 4; i++) {
                int f = i * 256 + tid;
                int r = f >> 3, c4 = (f & 7) << 2;
                As_u[r * (LDA_S/2) + (c4 >> 1)]     = pk_bf2(ra[i].x, ra[i].y);
                As_u[r * (LDA_S/2) + (c4 >> 1) + 1] = pk_bf2(ra[i].z, ra[i].w);
            }
        }
        #pragma unroll
        for (int i = 0; i < 4; i++) {
            int f = i * 256 + tid;
            int r = f >> 5, c4 = (f & 31) << 2;
            Bs_u[r * (LDB_S/2) + (c4 >> 1)]     = pk_bf2(rb[i].x, rb[i].y);
            Bs_u[r * (LDB_S/2) + (c4 >> 1) + 1] = pk_bf2(rb[i].z, rb[i].w);
        }
        __syncthreads();

        // prefetch next
        if (k0 + 32 < K) {
            if (!POSA) loadA(k0 + 32);
            loadB(k0 + 32);
        }

        // ---- mma over two k16 steps ----
        #pragma unroll
        for (int ks = 0; ks < 2; ks++) {
            uint32_t aregs[4][4], bregs[2][4];
            #pragma unroll
            for (int mt = 0; mt < 4; mt++) {
                uint32_t addr = asBase +
                    ((wm*64 + mt*16 + (lane & 15)) * LDA_S + ks*16 + (lane >> 4)*8) * 2;
                ldsm4(aregs[mt], addr);
            }
            #pragma unroll
            for (int j = 0; j < 2; j++) {
                uint32_t addr = bsBase +
                    ((ks*16 + (lane & 15)) * LDB_S + wn*32 + j*16 + (lane >> 4)*8) * 2;
                ldsm4t(bregs[j], addr);
            }
            #pragma unroll
            for (int mt = 0; mt < 4; mt++)
                #pragma unroll
                for (int nt = 0; nt < 4; nt++)
                    mma16816(acc[mt][nt], aregs[mt], &bregs[nt >> 1][(nt & 1) * 2]);
        }
        __syncthreads();
    }

    // ---- epilogue ----
    float bcol[4][2];
    #pragma unroll
    for (int nt = 0; nt < 4; nt++) {
        int col = nBase + wn*32 + nt*8 + (lane & 3)*2;
        bcol[nt][0] = bias[col];
        bcol[nt][1] = bias[col + 1];
    }
    #pragma unroll
    for (int mt = 0; mt < 4; mt++) {
        int row0 = mBase + wm*64 + mt*16 + (lane >> 2);
        #pragma unroll
        for (int half = 0; half < 2; half++) {
            int row = row0 + half*8;
            if (row >= M) continue;
            int gi = 0;
            if (GATHER) gi = gidx[row];
            #pragma unroll
            for (int nt = 0; nt < 4; nt++) {
                int col = nBase + wn*32 + nt*8 + (lane & 3)*2;
                float v0 = acc[mt][nt][half*2]     + bcol[nt][0];
                float v1 = acc[mt][nt][half*2 + 1] + bcol[nt][1];
                if (RELU) { v0 = fmaxf(v0, 0.f); v1 = fmaxf(v1, 0.f); }
                if (GATHER) {
                    const float* gp = gsrc + (size_t)gi * CDIM + col;
                    v0 += gp[0]; v1 += gp[1];
                }
                if (RES) {
                    const float* rp = res + (size_t)row * Nc + col;
                    v0 += rp[0]; v1 += rp[1];
                }
                *(float2*)(Cout + (size_t)row * Nc + col) = make_float2(v0, v1);
            }
        }
    }
}

// ---------------- attention: one block per window, thread = (q,h) pair ----------------
__global__ void __launch_bounds__(128) attn_kernel(
    const float* __restrict__ Qb, const float* __restrict__ Kb,
    const float* __restrict__ Vb, const int* __restrict__ kmask,
    float* __restrict__ Ao)
{
    __shared__ float sQ[SQL][CDIM];
    __shared__ float sKV[SKL][132];
    __shared__ int   sM[SKL];
    const int w = blockIdx.x;
    const int tid = threadIdx.x;
    const int h = tid & 7;
    const int q = tid >> 3;

    #pragma unroll
    for (int i = 0; i < 4; i++) {
        int f4 = i * 128 + tid;
        int r = f4 >> 5, c = (f4 & 31) * 4;
        *(float4*)(&sQ[r][c]) = *(const float4*)(Qb + (size_t)(w * SQL + r) * CDIM + c);
    }
    #pragma unroll
    for (int i = 0; i < 16; i++) {
        int f4 = i * 128 + tid;
        int r = f4 >> 5, c = (f4 & 31) * 4;
        *(float4*)(&sKV[r][c]) = *(const float4*)(Kb + (size_t)(w * SKL + r) * CDIM + c);
    }
    if (tid < SKL) sM[tid] = kmask[w * SKL + tid];
    __syncthreads();

    float qreg[16];
    #pragma unroll
    for (int j = 0; j < 4; j++)
        *(float4*)(qreg + j * 4) = *(const float4*)(&sQ[q][h * 16 + j * 4]);

    float s[SKL];
    #pragma unroll
    for (int k = 0; k < SKL; k++) {
        float4 v0 = *(const float4*)(&sKV[k][h * 16 + 0]);
        float4 v1 = *(const float4*)(&sKV[k][h * 16 + 4]);
        float4 v2 = *(const float4*)(&sKV[k][h * 16 + 8]);
        float4 v3 = *(const float4*)(&sKV[k][h * 16 + 12]);
        float acc = qreg[0]*v0.x + qreg[1]*v0.y + qreg[2]*v0.z + qreg[3]*v0.w
                  + qreg[4]*v1.x + qreg[5]*v1.y + qreg[6]*v1.z + qreg[7]*v1.w
                  + qreg[8]*v2.x + qreg[9]*v2.y + qreg[10]*v2.z + qreg[11]*v2.w
                  + qreg[12]*v3.x + qreg[13]*v3.y + qreg[14]*v3.z + qreg[15]*v3.w;
        s[k] = sM[k] ? -1e9f : acc * 0.25f;
    }
    float mx = -1e30f;
    #pragma unroll
    for (int k = 0; k < SKL; k++) mx = fmaxf(mx, s[k]);
    float sum = 0.f;
    #pragma unroll
    for (int k = 0; k < SKL; k++) { float e = expf(s[k] - mx); s[k] = e; sum += e; }
    float inv = 1.f / sum;
    #pragma unroll
    for (int k = 0; k < SKL; k++) s[k] *= inv;

    __syncthreads();
    #pragma unroll
    for (int i = 0; i < 16; i++) {
        int f4 = i * 128 + tid;
        int r = f4 >> 5, c = (f4 & 31) * 4;
        *(float4*)(&sKV[r][c]) = *(const float4*)(Vb + (size_t)(w * SKL + r) * CDIM + c);
    }
    __syncthreads();

    float4 o0 = make_float4(0,0,0,0), o1 = o0, o2 = o0, o3 = o0;
    #pragma unroll
    for (int k = 0; k < SKL; k++) {
        float p = s[k];
        float4 v0 = *(const float4*)(&sKV[k][h * 16 + 0]);
        float4 v1 = *(const float4*)(&sKV[k][h * 16 + 4]);
        float4 v2 = *(const float4*)(&sKV[k][h * 16 + 8]);
        float4 v3 = *(const float4*)(&sKV[k][h * 16 + 12]);
        o0.x = fmaf(p, v0.x, o0.x); o0.y = fmaf(p, v0.y, o0.y);
        o0.z = fmaf(p, v0.z, o0.z); o0.w = fmaf(p, v0.w, o0.w);
        o1.x = fmaf(p, v1.x, o1.x); o1.y = fmaf(p, v1.y, o1.y);
        o1.z = fmaf(p, v1.z, o1.z); o1.w = fmaf(p, v1.w, o1.w);
        o2.x = fmaf(p, v2.x, o2.x); o2.y = fmaf(p, v2.y, o2.y);
        o2.z = fmaf(p, v2.z, o2.z); o2.w = fmaf(p, v2.w, o2.w);
        o3.x = fmaf(p, v3.x, o3.x); o3.y = fmaf(p, v3.y, o3.y);
        o3.z = fmaf(p, v3.z, o3.z); o3.w = fmaf(p, v3.w, o3.w);
    }
    float* op = Ao + (size_t)(w * SQL + q) * CDIM + h * 16;
    *(float4*)(op + 0)  = o0;
    *(float4*)(op + 4)  = o1;
    *(float4*)(op + 8)  = o2;
    *(float4*)(op + 12) = o3;
}

// ---------------- scatter-mean support ----------------
__global__ void clear_kernel(float* __restrict__ sums, float* __restrict__ cnt)
{
    int i = blockIdx.x * blockDim.x + threadIdx.x;
    if (i < NPTS * CDIM) sums[i] = 0.f;
    if (i < NPTS) cnt[i] = 0.f;
}

__global__ void scatter_kernel(const int* __restrict__ qind, const int* __restrict__ qmask,
                               const float* __restrict__ ob,
                               float* __restrict__ sums, float* __restrict__ cnt)
{
    int e = blockIdx.x * blockDim.x + threadIdx.x;
    if (e >= TQ * CDIM) return;
    int t = e >> 7, c = e & 127;
    if (qmask[t] == 0) {
        int idx = qind[t];
        atomicAdd(&sums[(size_t)idx * CDIM + c], ob[e]);
        if (c == 0) atomicAdd(&cnt[idx], 1.0f);
    }
}

__global__ void resid_kernel(const float* __restrict__ feat, const float* __restrict__ sums,
                             const float* __restrict__ cnt, float* __restrict__ y)
{
    int e = blockIdx.x * blockDim.x + threadIdx.x;
    if (e >= NPTS * CDIM) return;
    int row = e >> 7;
    y[e] = feat[e] + sums[e] / fmaxf(cnt[row], 1.0f);
}

// ---------------- launch ----------------
extern "C" void kernel_launch(void* const* d_in, const int* in_sizes, int n_in,
                              void* d_out, int out_size)
{
    const float *features=nullptr, *q_pos=nullptr, *k_pos=nullptr;
    const float *ln1_g=nullptr, *ln1_b=nullptr, *pw1=nullptr, *pb1=nullptr;
    const float *pw2=nullptr, *pb2=nullptr;
    const float *wq=nullptr,*bq=nullptr,*wk=nullptr,*bk=nullptr,*wv=nullptr,*bv=nullptr,*wo=nullptr,*bo=nullptr;
    const float *ln2_g=nullptr,*ln2_b=nullptr,*fw1=nullptr,*fb1=nullptr,*fw2=nullptr,*fb2=nullptr;
    const int *q_ind=nullptr,*q_mask=nullptr,*k_ind=nullptr,*k_mask=nullptr;

    const float** slots128[11] = {&ln1_g,&ln1_b,&pb1,&pb2,&bq,&bk,&bv,&bo,&ln2_g,&ln2_b,&fb2};
    int c192=0, c768k=0, c16k=0, c64k=0, c128=0;
    for (int i = 0; i < n_in; i++) {
        int s = in_sizes[i];
        const void* p = d_in[i];
        if      (s == NPTS*CDIM)   features = (const float*)p;
        else if (s == NW*SQL*6)    q_pos = (const float*)p;
        else if (s == NW*SKL*6)    k_pos = (const float*)p;
        else if (s == NW*SQL)      { if (c192++ == 0) q_ind = (const int*)p; else q_mask = (const int*)p; }
        else if (s == NW*SKL)      { if (c768k++ == 0) k_ind = (const int*)p; else k_mask = (const int*)p; }
        else if (s == 6*CDIM)      pw1 = (const float*)p;
        else if (s == CDIM*CDIM) {
            const float* f = (const float*)p;
            switch (c16k++) { case 0: pw2=f; break; case 1: wq=f; break; case 2: wk=f; break;
                              case 3: wv=f; break; default: wo=f; break; }
        }
        else if (s == CDIM*FFD)    { if (c64k++ == 0) fw1 = (const float*)p; else fw2 = (const float*)p; }
        else if (s == FFD)         fb1 = (const float*)p;
        else if (s == CDIM)        { if (c128 < 11) *slots128[c128] = (const float*)p; c128++; }
    }

    float* arena = nullptr;
    cudaGetSymbolAddress((void**)&arena, g_arena);
    float* hb   = arena + O_H;
    float* qf   = arena + O_QF;
    float* kt   = arena + O_KT;
    float* Qb   = arena + O_Q;
    float* Kb   = arena + O_K;
    float* Vb   = arena + O_V;
    float* ao   = arena + O_AO;
    float* ob   = arena + O_OB;
    float* cnt  = arena + O_CNT;
    float* yb   = arena + O_Y;
    float* sums = arena + O_SUMS;
    float* h2b  = arena + O_H2;
    float* midb = arena + O_MID;
    float* out  = (float*)d_out;

    // 1. pre-norm
    ln_kernel<<<(NPTS*32 + 255)/256, 256>>>(features, ln1_g, ln1_b, hb, NPTS);
    // 2. fused pos-MLP + gather h[ind]
    gemm_mma<true,true,false,true><<<dim3(TQ/128, 1), 256>>>(q_pos, pw2, pb2, qf, TQ, CDIM, CDIM, q_ind, hb, nullptr, pw1, pb1);
    gemm_mma<true,true,false,true><<<dim3(TK/128, 1), 256>>>(k_pos, pw2, pb2, kt, TK, CDIM, CDIM, k_ind, hb, nullptr, pw1, pb1);
    // 3. Q/K/V projections
    gemm_mma<false,false,false,false><<<dim3(TQ/128, 1), 256>>>(qf, wq, bq, Qb, TQ, CDIM, CDIM, nullptr, nullptr, nullptr, nullptr, nullptr);
    gemm_mma<false,false,false,false><<<dim3(TK/128, 1), 256>>>(kt, wk, bk, Kb, TK, CDIM, CDIM, nullptr, nullptr, nullptr, nullptr, nullptr);
    gemm_mma<false,false,false,false><<<dim3(TK/128, 1), 256>>>(kt, wv, bv, Vb, TK, CDIM, CDIM, nullptr, nullptr, nullptr, nullptr, nullptr);
    // 4. windowed attention
    attn_kernel<<<NW, 128>>>(Qb, Kb, Vb, k_mask, ao);
    // 5. output projection
    gemm_mma<false,false,false,false><<<dim3(TQ/128, 1), 256>>>(ao, wo, bo, ob, TQ, CDIM, CDIM, nullptr, nullptr, nullptr, nullptr, nullptr);
    // 6. masked scatter-mean + residual
    clear_kernel<<<(NPTS*CDIM + 255)/256, 256>>>(sums, cnt);
    scatter_kernel<<<(TQ*CDIM + 255)/256, 256>>>(q_ind, q_mask, ob, sums, cnt);
    resid_kernel<<<(NPTS*CDIM + 255)/256, 256>>>(features, sums, cnt, yb);
    // 7. FFN with pre-norm + residual
    ln_kernel<<<(NPTS*32 + 255)/256, 256>>>(yb, ln2_g, ln2_b, h2b, NPTS);
    gemm_mma<true,false,false,false><<<dim3((NPTS + 127)/128, FFD/128), 256>>>(h2b, fw1, fb1, midb, NPTS, CDIM, FFD, nullptr, nullptr, nullptr, nullptr, nullptr);
    gemm_mma<false,false,true,false><<<dim3((NPTS + 127)/128, 1), 256>>>(midb, fw2, fb2, out, NPTS, FFD, CDIM, nullptr, nullptr, yb, nullptr, nullptr);
}

// round 5
// speedup vs baseline: 1.9367x; 1.0679x over previous
#include <cuda_runtime.h>
#include <cuda_bf16.h>
#include <cstddef>
#include <cstdint>

#define NPTS 120000
#define CDIM 128
#define NW   12000
#define SQL  16
#define SKL  64
#define FFD  512
#define TQ   (NW*SQL)   /* 192000 */
#define TK   (NW*SKL)   /* 768000 */

// ---------------- arena (float units) ----------------
// bf16 buffers occupy half-size float regions; fp32 buffers alias dead regions.
#define O_HB   ((size_t)0)                       /* h    bf16  7,680,000  */
#define O_QFB  ((size_t)7680000)                 /* qf   bf16 12,288,000  */
#define O_KTB  ((size_t)19968000)                /* kt   bf16 49,152,000  */
#define O_QB   ((size_t)69120000)                /* Q    bf16 12,288,000  */
#define O_KB   ((size_t)81408000)                /* K    bf16 49,152,000  */
#define O_VB   ((size_t)130560000)               /* V    bf16 49,152,000  */
#define ARENA_FLOATS ((size_t)179712000)

#define O_AOB  O_QFB                             /* ao   bf16 (qf dead)   */
#define O_OBB  O_KTB                             /* ob   bf16 (kt dead)   */
#define O_MIDB (O_KTB + (size_t)12288000)        /* mid  bf16 (after ob)  */
#define O_SUMS O_KB                              /* sums fp32 (K dead)    */
#define O_CNT  (O_KB + (size_t)15360000)         /* cnt  fp32             */
#define O_Y    (O_KB + (size_t)15480064)         /* y    fp32             */
#define O_H2B  O_QB                              /* h2   bf16 (Q dead)    */

__device__ float g_arena[ARENA_FLOATS];

// ---------------- PTX helpers ----------------
__device__ __forceinline__ uint32_t pk_bf2(float lo, float hi) {
    uint32_t r;
    asm("cvt.rn.bf16x2.f32 %0, %1, %2;" : "=r"(r) : "f"(hi), "f"(lo));
    return r;
}
__device__ __forceinline__ float2 bf2f(uint32_t u) {
    return __bfloat1622float2(*(__nv_bfloat162*)&u);
}
__device__ __forceinline__ void ldsm4(uint32_t* r, uint32_t addr) {
    asm volatile("ldmatrix.sync.aligned.m8n8.x4.shared.b16 {%0,%1,%2,%3}, [%4];"
        : "=r"(r[0]), "=r"(r[1]), "=r"(r[2]), "=r"(r[3]) : "r"(addr));
}
__device__ __forceinline__ void ldsm4t(uint32_t* r, uint32_t addr) {
    asm volatile("ldmatrix.sync.aligned.m8n8.x4.trans.shared.b16 {%0,%1,%2,%3}, [%4];"
        : "=r"(r[0]), "=r"(r[1]), "=r"(r[2]), "=r"(r[3]) : "r"(addr));
}
__device__ __forceinline__ void mma16816(float* d, const uint32_t* a, const uint32_t* b) {
    asm volatile("mma.sync.aligned.m16n8k16.row.col.f32.bf16.bf16.f32 "
        "{%0,%1,%2,%3}, {%4,%5,%6,%7}, {%8,%9}, {%0,%1,%2,%3};"
        : "+f"(d[0]), "+f"(d[1]), "+f"(d[2]), "+f"(d[3])
        : "r"(a[0]), "r"(a[1]), "r"(a[2]), "r"(a[3]), "r"(b[0]), "r"(b[1]));
}

// ---------------- LayerNorm (fp32 in, bf16 out) ----------------
__global__ void ln_kernel(const float* __restrict__ x, const float* __restrict__ g,
                          const float* __restrict__ b, __nv_bfloat16* __restrict__ out, int rows)
{
    int gid  = blockIdx.x * blockDim.x + threadIdx.x;
    int row  = gid >> 5;
    int lane = gid & 31;
    if (row >= rows) return;
    float4 v = *((const float4*)(x + (size_t)row * CDIM) + lane);
    float s  = v.x + v.y + v.z + v.w;
    float sq = v.x*v.x + v.y*v.y + v.z*v.z + v.w*v.w;
    #pragma unroll
    for (int o = 16; o > 0; o >>= 1) {
        s  += __shfl_xor_sync(0xffffffffu, s,  o);
        sq += __shfl_xor_sync(0xffffffffu, sq, o);
    }
    float m   = s * (1.0f / CDIM);
    float var = sq * (1.0f / CDIM) - m * m;
    float rs  = rsqrtf(var + 1e-5f);
    float4 gg = ((const float4*)g)[lane];
    float4 bb = ((const float4*)b)[lane];
    uint2 o2;
    o2.x = pk_bf2((v.x - m) * rs * gg.x + bb.x, (v.y - m) * rs * gg.y + bb.y);
    o2.y = pk_bf2((v.z - m) * rs * gg.z + bb.z, (v.w - m) * rs * gg.w + bb.w);
    *(uint2*)(out + (size_t)row * CDIM + lane * 4) = o2;
}

// ---------------- bf16 HMMA GEMM ----------------
// C = A[M,K] @ B[K,Nc]  (+bias)(relu)(+gather h[idx])(+residual)
// POSA: A = relu(pos@w1+b1) built in-tile.  else A is bf16.
// B fp32 (weights, converted). Output bf16 (OBF) or fp32.
#define LDA_S 40
#define LDB_S 136

template<bool RELU, bool GATHER, bool RES, bool POSA, bool OBF>
__global__ void __launch_bounds__(256) gemm_mma(
    const void* __restrict__ Ap, const float* __restrict__ B,
    const float* __restrict__ bias, void* __restrict__ Coutp,
    int M, int K, int Nc,
    const int* __restrict__ gidx, const __nv_bfloat16* __restrict__ gsrc,
    const float* __restrict__ res,
    const float* __restrict__ pw1, const float* __restrict__ pb1)
{
    __shared__ uint32_t As_u[128 * (LDA_S/2)];
    __shared__ uint32_t Bs_u[32 * (LDB_S/2)];
    __shared__ float    Wall[6*CDIM + CDIM];

    const int tid  = threadIdx.x;
    const int lane = tid & 31;
    const int wid  = tid >> 5;
    const int wm   = wid & 1;
    const int wn   = wid >> 1;
    const int mBase = blockIdx.x * 128;
    const int nBase = blockIdx.y * 128;

    const __nv_bfloat16* Abf = (const __nv_bfloat16*)Ap;
    const float*         Apos = (const float*)Ap;

    float preg[6];
    if (POSA) {
        const float* pp = Apos + (size_t)(mBase + (tid >> 1)) * 6;
        #pragma unroll
        for (int i = 0; i < 6; i++) preg[i] = pp[i];
        if (tid < 192) ((float4*)Wall)[tid] = ((const float4*)pw1)[tid];
        if (tid < 32)  ((float4*)(Wall + 6*CDIM))[tid] = ((const float4*)pb1)[tid];
        __syncthreads();
    }

    uint32_t asBase = (uint32_t)__cvta_generic_to_shared(As_u);
    uint32_t bsBase = (uint32_t)__cvta_generic_to_shared(Bs_u);

    float acc[4][4][4];
    #pragma unroll
    for (int mt = 0; mt < 4; mt++)
        #pragma unroll
        for (int nt = 0; nt < 4; nt++)
            #pragma unroll
            for (int i = 0; i < 4; i++) acc[mt][nt][i] = 0.f;

    uint4  rab[2];
    float4 rb[4];
    auto loadA = [&](int k0) {
        #pragma unroll
        for (int i = 0; i < 2; i++) {
            int f = i * 256 + tid;
            int r = f >> 2, c8 = (f & 3) << 3;
            int grow = mBase + r;
            rab[i] = (grow < M) ? *(const uint4*)(Abf + (size_t)grow * K + k0 + c8)
                                : make_uint4(0u, 0u, 0u, 0u);
        }
    };
    auto loadB = [&](int k0) {
        #pragma unroll
        for (int i = 0; i < 4; i++) {
            int f = i * 256 + tid;
            int r = f >> 5, c4 = (f & 31) << 2;
            rb[i] = *(const float4*)(B + (size_t)(k0 + r) * Nc + nBase + c4);
        }
    };

    if (!POSA) loadA(0);
    loadB(0);

    for (int k0 = 0; k0 < K; k0 += 32) {
        if (POSA) {
            const int row = tid >> 1;
            const int cb  = (tid & 1) * 16;
            #pragma unroll
            for (int cc = 0; cc < 16; cc += 2) {
                int kc = k0 + cb + cc;
                float v0 = Wall[6*CDIM + kc];
                float v1 = Wall[6*CDIM + kc + 1];
                #pragma unroll
                for (int i = 0; i < 6; i++) {
                    v0 = fmaf(preg[i], Wall[i*CDIM + kc],     v0);
                    v1 = fmaf(preg[i], Wall[i*CDIM + kc + 1], v1);
                }
                v0 = fmaxf(v0, 0.f); v1 = fmaxf(v1, 0.f);
                As_u[row * (LDA_S/2) + ((cb + cc) >> 1)] = pk_bf2(v0, v1);
            }
        } else {
            #pragma unroll
            for (int i = 0; i < 2; i++) {
                int f = i * 256 + tid;
                int r = f >> 2, c8 = (f & 3) << 3;
                *(uint4*)(&As_u[r * (LDA_S/2) + (c8 >> 1)]) = rab[i];
            }
        }
        #pragma unroll
        for (int i = 0; i < 4; i++) {
            int f = i * 256 + tid;
            int r = f >> 5, c4 = (f & 31) << 2;
            Bs_u[r * (LDB_S/2) + (c4 >> 1)]     = pk_bf2(rb[i].x, rb[i].y);
            Bs_u[r * (LDB_S/2) + (c4 >> 1) + 1] = pk_bf2(rb[i].z, rb[i].w);
        }
        __syncthreads();

        if (k0 + 32 < K) {
            if (!POSA) loadA(k0 + 32);
            loadB(k0 + 32);
        }

        #pragma unroll
        for (int ks = 0; ks < 2; ks++) {
            uint32_t aregs[4][4], bregs[2][4];
            #pragma unroll
            for (int mt = 0; mt < 4; mt++) {
                uint32_t addr = asBase +
                    ((wm*64 + mt*16 + (lane & 15)) * LDA_S + ks*16 + (lane >> 4)*8) * 2;
                ldsm4(aregs[mt], addr);
            }
            #pragma unroll
            for (int j = 0; j < 2; j++) {
                uint32_t addr = bsBase +
                    ((ks*16 + (lane & 15)) * LDB_S + wn*32 + j*16 + (lane >> 4)*8) * 2;
                ldsm4t(bregs[j], addr);
            }
            #pragma unroll
            for (int mt = 0; mt < 4; mt++)
                #pragma unroll
                for (int nt = 0; nt < 4; nt++)
                    mma16816(acc[mt][nt], aregs[mt], &bregs[nt >> 1][(nt & 1) * 2]);
        }
        __syncthreads();
    }

    // ---- epilogue ----
    float bcol[4][2];
    #pragma unroll
    for (int nt = 0; nt < 4; nt++) {
        int col = nBase + wn*32 + nt*8 + (lane & 3)*2;
        bcol[nt][0] = bias[col];
        bcol[nt][1] = bias[col + 1];
    }
    #pragma unroll
    for (int mt = 0; mt < 4; mt++) {
        int row0 = mBase + wm*64 + mt*16 + (lane >> 2);
        #pragma unroll
        for (int half = 0; half < 2; half++) {
            int row = row0 + half*8;
            if (row >= M) continue;
            int gi = 0;
            if (GATHER) gi = gidx[row];
            #pragma unroll
            for (int nt = 0; nt < 4; nt++) {
                int col = nBase + wn*32 + nt*8 + (lane & 3)*2;
                float v0 = acc[mt][nt][half*2]     + bcol[nt][0];
                float v1 = acc[mt][nt][half*2 + 1] + bcol[nt][1];
                if (RELU) { v0 = fmaxf(v0, 0.f); v1 = fmaxf(v1, 0.f); }
                if (GATHER) {
                    float2 g2 = bf2f(*(const uint32_t*)(gsrc + (size_t)gi * CDIM + col));
                    v0 += g2.x; v1 += g2.y;
                }
                if (RES) {
                    const float* rp = res + (size_t)row * Nc + col;
                    v0 += rp[0]; v1 += rp[1];
                }
                if (OBF) {
                    *(uint32_t*)((__nv_bfloat16*)Coutp + (size_t)row * Nc + col) = pk_bf2(v0, v1);
                } else {
                    *(float2*)((float*)Coutp + (size_t)row * Nc + col) = make_float2(v0, v1);
                }
            }
        }
    }
}

// ---------------- attention: bf16 in/out, fp32 math in smem/registers ----------------
__global__ void __launch_bounds__(128) attn_kernel(
    const __nv_bfloat16* __restrict__ Qb, const __nv_bfloat16* __restrict__ Kb,
    const __nv_bfloat16* __restrict__ Vb, const int* __restrict__ kmask,
    __nv_bfloat16* __restrict__ Ao)
{
    __shared__ float sQ[SQL][CDIM];
    __shared__ float sKV[SKL][132];
    __shared__ int   sM[SKL];
    const int w = blockIdx.x;
    const int tid = threadIdx.x;
    const int h = tid & 7;
    const int q = tid >> 3;

    #pragma unroll
    for (int i = 0; i < 2; i++) {
        int f = i * 128 + tid;
        int r = f >> 4, c8 = (f & 15) * 8;
        uint4 u = *(const uint4*)(Qb + (size_t)(w * SQL + r) * CDIM + c8);
        float2 a = bf2f(u.x), b = bf2f(u.y), c = bf2f(u.z), d = bf2f(u.w);
        sQ[r][c8+0]=a.x; sQ[r][c8+1]=a.y; sQ[r][c8+2]=b.x; sQ[r][c8+3]=b.y;
        sQ[r][c8+4]=c.x; sQ[r][c8+5]=c.y; sQ[r][c8+6]=d.x; sQ[r][c8+7]=d.y;
    }
    #pragma unroll
    for (int i = 0; i < 8; i++) {
        int f = i * 128 + tid;
        int r = f >> 4, c8 = (f & 15) * 8;
        uint4 u = *(const uint4*)(Kb + (size_t)(w * SKL + r) * CDIM + c8);
        float2 a = bf2f(u.x), b = bf2f(u.y), c = bf2f(u.z), d = bf2f(u.w);
        sKV[r][c8+0]=a.x; sKV[r][c8+1]=a.y; sKV[r][c8+2]=b.x; sKV[r][c8+3]=b.y;
        sKV[r][c8+4]=c.x; sKV[r][c8+5]=c.y; sKV[r][c8+6]=d.x; sKV[r][c8+7]=d.y;
    }
    if (tid < SKL) sM[tid] = kmask[w * SKL + tid];
    __syncthreads();

    float qreg[16];
    #pragma unroll
    for (int j = 0; j < 4; j++)
        *(float4*)(qreg + j * 4) = *(const float4*)(&sQ[q][h * 16 + j * 4]);

    float s[SKL];
    #pragma unroll
    for (int k = 0; k < SKL; k++) {
        float4 v0 = *(const float4*)(&sKV[k][h * 16 + 0]);
        float4 v1 = *(const float4*)(&sKV[k][h * 16 + 4]);
        float4 v2 = *(const float4*)(&sKV[k][h * 16 + 8]);
        float4 v3 = *(const float4*)(&sKV[k][h * 16 + 12]);
        float acc = qreg[0]*v0.x + qreg[1]*v0.y + qreg[2]*v0.z + qreg[3]*v0.w
                  + qreg[4]*v1.x + qreg[5]*v1.y + qreg[6]*v1.z + qreg[7]*v1.w
                  + qreg[8]*v2.x + qreg[9]*v2.y + qreg[10]*v2.z + qreg[11]*v2.w
                  + qreg[12]*v3.x + qreg[13]*v3.y + qreg[14]*v3.z + qreg[15]*v3.w;
        s[k] = sM[k] ? -1e9f : acc * 0.25f;
    }
    float mx = -1e30f;
    #pragma unroll
    for (int k = 0; k < SKL; k++) mx = fmaxf(mx, s[k]);
    float sum = 0.f;
    #pragma unroll
    for (int k = 0; k < SKL; k++) { float e = expf(s[k] - mx); s[k] = e; sum += e; }
    float inv = 1.f / sum;
    #pragma unroll
    for (int k = 0; k < SKL; k++) s[k] *= inv;

    __syncthreads();
    #pragma unroll
    for (int i = 0; i < 8; i++) {
        int f = i * 128 + tid;
        int r = f >> 4, c8 = (f & 15) * 8;
        uint4 u = *(const uint4*)(Vb + (size_t)(w * SKL + r) * CDIM + c8);
        float2 a = bf2f(u.x), b = bf2f(u.y), c = bf2f(u.z), d = bf2f(u.w);
        sKV[r][c8+0]=a.x; sKV[r][c8+1]=a.y; sKV[r][c8+2]=b.x; sKV[r][c8+3]=b.y;
        sKV[r][c8+4]=c.x; sKV[r][c8+5]=c.y; sKV[r][c8+6]=d.x; sKV[r][c8+7]=d.y;
    }
    __syncthreads();

    float4 o0 = make_float4(0,0,0,0), o1 = o0, o2 = o0, o3 = o0;
    #pragma unroll
    for (int k = 0; k < SKL; k++) {
        float p = s[k];
        float4 v0 = *(const float4*)(&sKV[k][h * 16 + 0]);
        float4 v1 = *(const float4*)(&sKV[k][h * 16 + 4]);
        float4 v2 = *(const float4*)(&sKV[k][h * 16 + 8]);
        float4 v3 = *(const float4*)(&sKV[k][h * 16 + 12]);
        o0.x = fmaf(p, v0.x, o0.x); o0.y = fmaf(p, v0.y, o0.y);
        o0.z = fmaf(p, v0.z, o0.z); o0.w = fmaf(p, v0.w, o0.w);
        o1.x = fmaf(p, v1.x, o1.x); o1.y = fmaf(p, v1.y, o1.y);
        o1.z = fmaf(p, v1.z, o1.z); o1.w = fmaf(p, v1.w, o1.w);
        o2.x = fmaf(p, v2.x, o2.x); o2.y = fmaf(p, v2.y, o2.y);
        o2.z = fmaf(p, v2.z, o2.z); o2.w = fmaf(p, v2.w, o2.w);
        o3.x = fmaf(p, v3.x, o3.x); o3.y = fmaf(p, v3.y, o3.y);
        o3.z = fmaf(p, v3.z, o3.z); o3.w = fmaf(p, v3.w, o3.w);
    }
    uint4 pa, pb;
    pa.x = pk_bf2(o0.x, o0.y); pa.y = pk_bf2(o0.z, o0.w);
    pa.z = pk_bf2(o1.x, o1.y); pa.w = pk_bf2(o1.z, o1.w);
    pb.x = pk_bf2(o2.x, o2.y); pb.y = pk_bf2(o2.z, o2.w);
    pb.z = pk_bf2(o3.x, o3.y); pb.w = pk_bf2(o3.z, o3.w);
    __nv_bfloat16* op = Ao + (size_t)(w * SQL + q) * CDIM + h * 16;
    *(uint4*)(op)     = pa;
    *(uint4*)(op + 8) = pb;
}

// ---------------- scatter-mean support ----------------
__global__ void clear_kernel(float* __restrict__ sums, float* __restrict__ cnt)
{
    int i = blockIdx.x * blockDim.x + threadIdx.x;
    if (i < NPTS * CDIM) sums[i] = 0.f;
    if (i < NPTS) cnt[i] = 0.f;
}

__global__ void scatter_kernel(const int* __restrict__ qind, const int* __restrict__ qmask,
                               const __nv_bfloat16* __restrict__ ob,
                               float* __restrict__ sums, float* __restrict__ cnt)
{
    int e = blockIdx.x * blockDim.x + threadIdx.x;
    if (e >= TQ * CDIM / 2) return;
    int t = e >> 6, c2 = (e & 63) * 2;
    if (qmask[t] == 0) {
        int idx = qind[t];
        float2 f = bf2f(*(const uint32_t*)(ob + (size_t)e * 2));
        atomicAdd(&sums[(size_t)idx * CDIM + c2],     f.x);
        atomicAdd(&sums[(size_t)idx * CDIM + c2 + 1], f.y);
        if (c2 == 0) atomicAdd(&cnt[idx], 1.0f);
    }
}

__global__ void resid_kernel(const float* __restrict__ feat, const float* __restrict__ sums,
                             const float* __restrict__ cnt, float* __restrict__ y)
{
    int e = blockIdx.x * blockDim.x + threadIdx.x;
    if (e >= NPTS * CDIM) return;
    int row = e >> 7;
    y[e] = feat[e] + sums[e] / fmaxf(cnt[row], 1.0f);
}

// ---------------- launch ----------------
extern "C" void kernel_launch(void* const* d_in, const int* in_sizes, int n_in,
                              void* d_out, int out_size)
{
    const float *features=nullptr, *q_pos=nullptr, *k_pos=nullptr;
    const float *ln1_g=nullptr, *ln1_b=nullptr, *pw1=nullptr, *pb1=nullptr;
    const float *pw2=nullptr, *pb2=nullptr;
    const float *wq=nullptr,*bq=nullptr,*wk=nullptr,*bk=nullptr,*wv=nullptr,*bv=nullptr,*wo=nullptr,*bo=nullptr;
    const float *ln2_g=nullptr,*ln2_b=nullptr,*fw1=nullptr,*fb1=nullptr,*fw2=nullptr,*fb2=nullptr;
    const int *q_ind=nullptr,*q_mask=nullptr,*k_ind=nullptr,*k_mask=nullptr;

    const float** slots128[11] = {&ln1_g,&ln1_b,&pb1,&pb2,&bq,&bk,&bv,&bo,&ln2_g,&ln2_b,&fb2};
    int c192=0, c768k=0, c16k=0, c64k=0, c128=0;
    for (int i = 0; i < n_in; i++) {
        int s = in_sizes[i];
        const void* p = d_in[i];
        if      (s == NPTS*CDIM)   features = (const float*)p;
        else if (s == NW*SQL*6)    q_pos = (const float*)p;
        else if (s == NW*SKL*6)    k_pos = (const float*)p;
        else if (s == NW*SQL)      { if (c192++ == 0) q_ind = (const int*)p; else q_mask = (const int*)p; }
        else if (s == NW*SKL)      { if (c768k++ == 0) k_ind = (const int*)p; else k_mask = (const int*)p; }
        else if (s == 6*CDIM)      pw1 = (const float*)p;
        else if (s == CDIM*CDIM) {
            const float* f = (const float*)p;
            switch (c16k++) { case 0: pw2=f; break; case 1: wq=f; break; case 2: wk=f; break;
                              case 3: wv=f; break; default: wo=f; break; }
        }
        else if (s == CDIM*FFD)    { if (c64k++ == 0) fw1 = (const float*)p; else fw2 = (const float*)p; }
        else if (s == FFD)         fb1 = (const float*)p;
        else if (s == CDIM)        { if (c128 < 11) *slots128[c128] = (const float*)p; c128++; }
    }

    float* arena = nullptr;
    cudaGetSymbolAddress((void**)&arena, g_arena);
    __nv_bfloat16* hb  = (__nv_bfloat16*)(arena + O_HB);
    __nv_bfloat16* qf  = (__nv_bfloat16*)(arena + O_QFB);
    __nv_bfloat16* kt  = (__nv_bfloat16*)(arena + O_KTB);
    __nv_bfloat16* Qb  = (__nv_bfloat16*)(arena + O_QB);
    __nv_bfloat16* Kb  = (__nv_bfloat16*)(arena + O_KB);
    __nv_bfloat16* Vb  = (__nv_bfloat16*)(arena + O_VB);
    __nv_bfloat16* ao  = (__nv_bfloat16*)(arena + O_AOB);
    __nv_bfloat16* ob  = (__nv_bfloat16*)(arena + O_OBB);
    __nv_bfloat16* mid = (__nv_bfloat16*)(arena + O_MIDB);
    __nv_bfloat16* h2b = (__nv_bfloat16*)(arena + O_H2B);
    float* sums = arena + O_SUMS;
    float* cnt  = arena + O_CNT;
    float* yb   = arena + O_Y;
    float* out  = (float*)d_out;

    // 1. pre-norm (bf16 out)
    ln_kernel<<<(NPTS*32 + 255)/256, 256>>>(features, ln1_g, ln1_b, hb, NPTS);
    // 2. fused pos-MLP + gather h[ind] (bf16 out)
    gemm_mma<true,true,false,true,true><<<dim3(TQ/128, 1), 256>>>(q_pos, pw2, pb2, qf, TQ, CDIM, CDIM, q_ind, hb, nullptr, pw1, pb1);
    gemm_mma<true,true,false,true,true><<<dim3(TK/128, 1), 256>>>(k_pos, pw2, pb2, kt, TK, CDIM, CDIM, k_ind, hb, nullptr, pw1, pb1);
    // 3. Q/K/V projections (bf16 in/out)
    gemm_mma<false,false,false,false,true><<<dim3(TQ/128, 1), 256>>>(qf, wq, bq, Qb, TQ, CDIM, CDIM, nullptr, nullptr, nullptr, nullptr, nullptr);
    gemm_mma<false,false,false,false,true><<<dim3(TK/128, 1), 256>>>(kt, wk, bk, Kb, TK, CDIM, CDIM, nullptr, nullptr, nullptr, nullptr, nullptr);
    gemm_mma<false,false,false,false,true><<<dim3(TK/128, 1), 256>>>(kt, wv, bv, Vb, TK, CDIM, CDIM, nullptr, nullptr, nullptr, nullptr, nullptr);
    // 4. windowed attention
    attn_kernel<<<NW, 128>>>(Qb, Kb, Vb, k_mask, ao);
    // 5. output projection
    gemm_mma<false,false,false,false,true><<<dim3(TQ/128, 1), 256>>>(ao, wo, bo, ob, TQ, CDIM, CDIM, nullptr, nullptr, nullptr, nullptr, nullptr);
    // 6. masked scatter-mean + residual
    clear_kernel<<<(NPTS*CDIM + 255)/256, 256>>>(sums, cnt);
    scatter_kernel<<<(TQ*CDIM/2 + 255)/256, 256>>>(q_ind, q_mask, ob, sums, cnt);
    resid_kernel<<<(NPTS*CDIM + 255)/256, 256>>>(features, sums, cnt, yb);
    // 7. FFN with pre-norm + residual
    ln_kernel<<<(NPTS*32 + 255)/256, 256>>>(yb, ln2_g, ln2_b, h2b, NPTS);
    gemm_mma<true,false,false,false,true><<<dim3((NPTS + 127)/128, FFD/128), 256>>>(h2b, fw1, fb1, mid, NPTS, CDIM, FFD, nullptr, nullptr, nullptr, nullptr, nullptr);
    gemm_mma<false,false,true,false,false><<<dim3((NPTS + 127)/128, 1), 256>>>(mid, fw2, fb2, out, NPTS, FFD, CDIM, nullptr, nullptr, yb, nullptr, nullptr);
}

// round 6
// speedup vs baseline: 2.1460x; 1.1081x over previous
#include <cuda_runtime.h>
#include <cuda_bf16.h>
#include <cstddef>
#include <cstdint>

#define NPTS 120000
#define CDIM 128
#define NW   12000
#define SQL  16
#define SKL  64
#define FFD  512
#define TQ   (NW*SQL)   /* 192000 */
#define TK   (NW*SKL)   /* 768000 */

// ---------------- arena (float units) ----------------
#define O_HB   ((size_t)0)                        /* h    bf16  -> 7.68M fl   */
#define O_QB   ((size_t)7680000)                  /* Q    bf16  -> 12.288M fl */
#define O_KB   ((size_t)19968000)                 /* K    bf16  -> 49.152M fl */
#define O_VB   ((size_t)69120000)                 /* V    bf16  -> 49.152M fl */
#define O_AOB  ((size_t)118272000)                /* ao   bf16  -> 12.288M fl */
#define ARENA_FLOATS ((size_t)130560000)          /* 522 MB */

#define O_OBB  O_KB                               /* ob  bf16 (K dead)        */
#define O_MIDB (O_KB + (size_t)12288000)          /* mid bf16 (30.72M fl)     */
#define O_SUMS O_VB                               /* sums fp32 (V dead)       */
#define O_CNT  (O_VB + (size_t)15360000)          /* cnt fp32                 */
#define O_Y    (O_VB + (size_t)15480064)          /* y   fp32                 */
#define O_H2B  O_QB                               /* h2  bf16 (Q dead)        */

__device__ float g_arena[ARENA_FLOATS];

// bf16 weight cache: [pw2|wq|wk|wv|wo|fw1|fw2]
#define W_PW2 0
#define W_WQ  16384
#define W_WK  32768
#define W_WV  49152
#define W_WO  65536
#define W_FW1 81920
#define W_FW2 147456
__device__ __nv_bfloat16 g_wbuf[212992];

// ---------------- PTX helpers ----------------
__device__ __forceinline__ uint32_t pk_bf2(float lo, float hi) {
    uint32_t r;
    asm("cvt.rn.bf16x2.f32 %0, %1, %2;" : "=r"(r) : "f"(hi), "f"(lo));
    return r;
}
__device__ __forceinline__ float2 bf2f(uint32_t u) {
    return __bfloat1622float2(*(__nv_bfloat162*)&u);
}
__device__ __forceinline__ void ldsm4(uint32_t* r, uint32_t addr) {
    asm volatile("ldmatrix.sync.aligned.m8n8.x4.shared.b16 {%0,%1,%2,%3}, [%4];"
        : "=r"(r[0]), "=r"(r[1]), "=r"(r[2]), "=r"(r[3]) : "r"(addr));
}
__device__ __forceinline__ void ldsm4t(uint32_t* r, uint32_t addr) {
    asm volatile("ldmatrix.sync.aligned.m8n8.x4.trans.shared.b16 {%0,%1,%2,%3}, [%4];"
        : "=r"(r[0]), "=r"(r[1]), "=r"(r[2]), "=r"(r[3]) : "r"(addr));
}
__device__ __forceinline__ void mma16816(float* d, const uint32_t* a, const uint32_t* b) {
    asm volatile("mma.sync.aligned.m16n8k16.row.col.f32.bf16.bf16.f32 "
        "{%0,%1,%2,%3}, {%4,%5,%6,%7}, {%8,%9}, {%0,%1,%2,%3};"
        : "+f"(d[0]), "+f"(d[1]), "+f"(d[2]), "+f"(d[3])
        : "r"(a[0]), "r"(a[1]), "r"(a[2]), "r"(a[3]), "r"(b[0]), "r"(b[1]));
}

// ---------------- weight convert (once per graph replay; deterministic) ----------------
__global__ void convert_w(const float* __restrict__ pw2, const float* __restrict__ wq,
                          const float* __restrict__ wk,  const float* __restrict__ wv,
                          const float* __restrict__ wo,  const float* __restrict__ fw1,
                          const float* __restrict__ fw2)
{
    int b = blockIdx.x, t = threadIdx.x;
    const float* src; int base, idx;
    if      (b <  64) { src = pw2; base = W_PW2; idx = b*256 + t; }
    else if (b < 128) { src = wq;  base = W_WQ;  idx = (b-64)*256 + t; }
    else if (b < 192) { src = wk;  base = W_WK;  idx = (b-128)*256 + t; }
    else if (b < 256) { src = wv;  base = W_WV;  idx = (b-192)*256 + t; }
    else if (b < 320) { src = wo;  base = W_WO;  idx = (b-256)*256 + t; }
    else if (b < 576) { src = fw1; base = W_FW1; idx = (b-320)*256 + t; }
    else              { src = fw2; base = W_FW2; idx = (b-576)*256 + t; }
    g_wbuf[base + idx] = __float2bfloat16(src[idx]);
}

// ---------------- LayerNorm (fp32 in, bf16 out) ----------------
__global__ void ln_kernel(const float* __restrict__ x, const float* __restrict__ g,
                          const float* __restrict__ b, __nv_bfloat16* __restrict__ out, int rows)
{
    int gid  = blockIdx.x * blockDim.x + threadIdx.x;
    int row  = gid >> 5;
    int lane = gid & 31;
    if (row >= rows) return;
    float4 v = *((const float4*)(x + (size_t)row * CDIM) + lane);
    float s  = v.x + v.y + v.z + v.w;
    float sq = v.x*v.x + v.y*v.y + v.z*v.z + v.w*v.w;
    #pragma unroll
    for (int o = 16; o > 0; o >>= 1) {
        s  += __shfl_xor_sync(0xffffffffu, s,  o);
        sq += __shfl_xor_sync(0xffffffffu, sq, o);
    }
    float m   = s * (1.0f / CDIM);
    float var = sq * (1.0f / CDIM) - m * m;
    float rs  = rsqrtf(var + 1e-5f);
    float4 gg = ((const float4*)g)[lane];
    float4 bb = ((const float4*)b)[lane];
    uint2 o2;
    o2.x = pk_bf2((v.x - m) * rs * gg.x + bb.x, (v.y - m) * rs * gg.y + bb.y);
    o2.y = pk_bf2((v.z - m) * rs * gg.z + bb.z, (v.w - m) * rs * gg.w + bb.w);
    *(uint2*)(out + (size_t)row * CDIM + lane * 4) = o2;
}

// ================= fused chain GEMM =================
// Phase 1: C1 = relu(pos@w1 + b1)@pw2 + pb2, relu, + h[gidx]   (kept in SMEM, bf16)
// Phase 2: out_j = C1 @ w2_j + b2_j   for j < NOUT
// BM=128, BN=128, BK=32, 256 threads (8 warps: 2m x 4n)
#define LDA_S 40    /* phase-1 As: bf16/row (32+8) */
#define LDB_S 136   /* Bs & C1: bf16/row (128+8)   */

template<int NOUT>
__global__ void __launch_bounds__(256) gemm2_mma(
    const float* __restrict__ pos,
    const float* __restrict__ pw1, const float* __restrict__ pb1,
    const __nv_bfloat16* __restrict__ pw2bf, const float* __restrict__ pb2,
    const int* __restrict__ gidx, const __nv_bfloat16* __restrict__ gsrc,
    const __nv_bfloat16* __restrict__ w2a, const float* __restrict__ b2a, __nv_bfloat16* __restrict__ outa,
    const __nv_bfloat16* __restrict__ w2b, const float* __restrict__ b2b, __nv_bfloat16* __restrict__ outb)
{
    __shared__ __align__(16) char sbuf[47104];
    uint32_t* C1_u = (uint32_t*)sbuf;             // 128 x (LDB_S/2), phase 2 A source
    uint32_t* As_u = (uint32_t*)sbuf;             // 128 x (LDA_S/2), phase-1 only (overlaps C1)
    uint32_t* Bs_u = (uint32_t*)(sbuf + 34816);   // 32 x (LDB_S/2)
    float*    Wall = (float*)(sbuf + 43520);      // w1(6x128)+b1(128)

    const int tid = threadIdx.x, lane = tid & 31, wid = tid >> 5;
    const int wm = wid & 1, wn = wid >> 1;
    const int mBase = blockIdx.x * 128;

    float preg[6];
    {
        const float* pp = pos + (size_t)(mBase + (tid >> 1)) * 6;
        #pragma unroll
        for (int i = 0; i < 6; i++) preg[i] = pp[i];
    }
    if (tid < 192) ((float4*)Wall)[tid] = ((const float4*)pw1)[tid];
    if (tid < 32)  ((float4*)(Wall + 6*CDIM))[tid] = ((const float4*)pb1)[tid];
    __syncthreads();

    uint32_t asB = (uint32_t)__cvta_generic_to_shared(As_u);
    uint32_t bsB = (uint32_t)__cvta_generic_to_shared(Bs_u);

    float acc[4][4][4];
    #pragma unroll
    for (int mt = 0; mt < 4; mt++)
        #pragma unroll
        for (int nt = 0; nt < 4; nt++)
            #pragma unroll
            for (int i = 0; i < 4; i++) acc[mt][nt][i] = 0.f;

    uint4 rbb[2];
    auto loadBW = [&](const __nv_bfloat16* W, int k0) {
        #pragma unroll
        for (int i = 0; i < 2; i++) {
            int f = i * 256 + tid;
            int r = f >> 4, c8 = (f & 15) * 8;
            rbb[i] = *(const uint4*)(W + (size_t)(k0 + r) * CDIM + c8);
        }
    };
    auto storeBs = [&]() {
        #pragma unroll
        for (int i = 0; i < 2; i++) {
            int f = i * 256 + tid;
            int r = f >> 4;
            *(uint4*)&Bs_u[r * (LDB_S/2) + (f & 15) * 4] = rbb[i];
        }
    };

    // ---------- phase 1 ----------
    loadBW(pw2bf, 0);
    for (int k0 = 0; k0 < 128; k0 += 32) {
        {
            const int row = tid >> 1;
            const int cb  = (tid & 1) * 16;
            #pragma unroll
            for (int cc = 0; cc < 16; cc += 2) {
                int kc = k0 + cb + cc;
                float v0 = Wall[6*CDIM + kc];
                float v1 = Wall[6*CDIM + kc + 1];
                #pragma unroll
                for (int i = 0; i < 6; i++) {
                    v0 = fmaf(preg[i], Wall[i*CDIM + kc],     v0);
                    v1 = fmaf(preg[i], Wall[i*CDIM + kc + 1], v1);
                }
                As_u[row * (LDA_S/2) + ((cb + cc) >> 1)] = pk_bf2(fmaxf(v0, 0.f), fmaxf(v1, 0.f));
            }
        }
        storeBs();
        __syncthreads();
        if (k0 + 32 < 128) loadBW(pw2bf, k0 + 32);
        #pragma unroll
        for (int ks = 0; ks < 2; ks++) {
            uint32_t aregs[4][4], bregs[2][4];
            #pragma unroll
            for (int mt = 0; mt < 4; mt++) {
                uint32_t addr = asB +
                    ((wm*64 + mt*16 + (lane & 15)) * LDA_S + ks*16 + (lane >> 4)*8) * 2;
                ldsm4(aregs[mt], addr);
            }
            #pragma unroll
            for (int j = 0; j < 2; j++) {
                uint32_t addr = bsB +
                    ((ks*16 + (lane & 15)) * LDB_S + wn*32 + j*16 + (lane >> 4)*8) * 2;
                ldsm4t(bregs[j], addr);
            }
            #pragma unroll
            for (int mt = 0; mt < 4; mt++)
                #pragma unroll
                for (int nt = 0; nt < 4; nt++)
                    mma16816(acc[mt][nt], aregs[mt], &bregs[nt >> 1][(nt & 1) * 2]);
        }
        __syncthreads();
    }

    // phase-1 epilogue -> C1 smem (overlays As; all As reads done)
    {
        float bc[4][2];
        #pragma unroll
        for (int nt = 0; nt < 4; nt++) {
            int col = wn*32 + nt*8 + (lane & 3)*2;
            bc[nt][0] = pb2[col];
            bc[nt][1] = pb2[col + 1];
        }
        #pragma unroll
        for (int mt = 0; mt < 4; mt++) {
            #pragma unroll
            for (int half = 0; half < 2; half++) {
                int rl = wm*64 + mt*16 + (lane >> 2) + half*8;
                int gi = gidx[mBase + rl];
                #pragma unroll
                for (int nt = 0; nt < 4; nt++) {
                    int col = wn*32 + nt*8 + (lane & 3)*2;
                    float v0 = fmaxf(acc[mt][nt][half*2]     + bc[nt][0], 0.f);
                    float v1 = fmaxf(acc[mt][nt][half*2 + 1] + bc[nt][1], 0.f);
                    float2 g2 = bf2f(*(const uint32_t*)(gsrc + (size_t)gi * CDIM + col));
                    v0 += g2.x; v1 += g2.y;
                    C1_u[rl * (LDB_S/2) + (col >> 1)] = pk_bf2(v0, v1);
                }
            }
        }
    }
    __syncthreads();

    // ---------- phase 2: out_j = C1 @ w2_j + b2_j ----------
    #pragma unroll
    for (int j = 0; j < NOUT; j++) {
        const __nv_bfloat16* W = (j == 0) ? w2a : w2b;
        const float* b2        = (j == 0) ? b2a : b2b;
        __nv_bfloat16* outp    = (j == 0) ? outa : outb;

        #pragma unroll
        for (int mt = 0; mt < 4; mt++)
            #pragma unroll
            for (int nt = 0; nt < 4; nt++)
                #pragma unroll
                for (int i = 0; i < 4; i++) acc[mt][nt][i] = 0.f;

        loadBW(W, 0);
        for (int k0 = 0; k0 < 128; k0 += 32) {
            __syncthreads();                 // Bs consumers from previous chunk done
            storeBs();
            __syncthreads();
            if (k0 + 32 < 128) loadBW(W, k0 + 32);
            #pragma unroll
            for (int ks = 0; ks < 2; ks++) {
                uint32_t aregs[4][4], bregs[2][4];
                #pragma unroll
                for (int mt = 0; mt < 4; mt++) {
                    uint32_t addr = asB +
                        ((wm*64 + mt*16 + (lane & 15)) * LDB_S + k0 + ks*16 + (lane >> 4)*8) * 2;
                    ldsm4(aregs[mt], addr);
                }
                #pragma unroll
                for (int jj = 0; jj < 2; jj++) {
                    uint32_t addr = bsB +
                        ((ks*16 + (lane & 15)) * LDB_S + wn*32 + jj*16 + (lane >> 4)*8) * 2;
                    ldsm4t(bregs[jj], addr);
                }
                #pragma unroll
                for (int mt = 0; mt < 4; mt++)
                    #pragma unroll
                    for (int nt = 0; nt < 4; nt++)
                        mma16816(acc[mt][nt], aregs[mt], &bregs[nt >> 1][(nt & 1) * 2]);
            }
        }

        float bc[4][2];
        #pragma unroll
        for (int nt = 0; nt < 4; nt++) {
            int col = wn*32 + nt*8 + (lane & 3)*2;
            bc[nt][0] = b2[col];
            bc[nt][1] = b2[col + 1];
        }
        #pragma unroll
        for (int mt = 0; mt < 4; mt++) {
            #pragma unroll
            for (int half = 0; half < 2; half++) {
                int rl = wm*64 + mt*16 + (lane >> 2) + half*8;
                #pragma unroll
                for (int nt = 0; nt < 4; nt++) {
                    int col = wn*32 + nt*8 + (lane & 3)*2;
                    float v0 = acc[mt][nt][half*2]     + bc[nt][0];
                    float v1 = acc[mt][nt][half*2 + 1] + bc[nt][1];
                    *(uint32_t*)(outp + (size_t)(mBase + rl) * CDIM + col) = pk_bf2(v0, v1);
                }
            }
        }
    }
}

// ---------------- plain bf16 GEMM (bf16 A, bf16 B) ----------------
template<bool RELU, bool RES, bool OBF>
__global__ void __launch_bounds__(256) gemm_mma(
    const __nv_bfloat16* __restrict__ A, const __nv_bfloat16* __restrict__ B,
    const float* __restrict__ bias, void* __restrict__ Coutp,
    int M, int K, int Nc, const float* __restrict__ res)
{
    __shared__ uint32_t As_u[128 * (LDA_S/2)];
    __shared__ uint32_t Bs_u[32 * (LDB_S/2)];

    const int tid  = threadIdx.x;
    const int lane = tid & 31;
    const int wid  = tid >> 5;
    const int wm   = wid & 1;
    const int wn   = wid >> 1;
    const int mBase = blockIdx.x * 128;
    const int nBase = blockIdx.y * 128;

    uint32_t asBase = (uint32_t)__cvta_generic_to_shared(As_u);
    uint32_t bsBase = (uint32_t)__cvta_generic_to_shared(Bs_u);

    float acc[4][4][4];
    #pragma unroll
    for (int mt = 0; mt < 4; mt++)
        #pragma unroll
        for (int nt = 0; nt < 4; nt++)
            #pragma unroll
            for (int i = 0; i < 4; i++) acc[mt][nt][i] = 0.f;

    uint4 rab[2], rbb[2];
    auto loadA = [&](int k0) {
        #pragma unroll
        for (int i = 0; i < 2; i++) {
            int f = i * 256 + tid;
            int r = f >> 2, c8 = (f & 3) << 3;
            int grow = mBase + r;
            rab[i] = (grow < M) ? *(const uint4*)(A + (size_t)grow * K + k0 + c8)
                                : make_uint4(0u, 0u, 0u, 0u);
        }
    };
    auto loadB = [&](int k0) {
        #pragma unroll
        for (int i = 0; i < 2; i++) {
            int f = i * 256 + tid;
            int r = f >> 4, c8 = (f & 15) * 8;
            rbb[i] = *(const uint4*)(B + (size_t)(k0 + r) * Nc + nBase + c8);
        }
    };

    loadA(0);
    loadB(0);

    for (int k0 = 0; k0 < K; k0 += 32) {
        #pragma unroll
        for (int i = 0; i < 2; i++) {
            int f = i * 256 + tid;
            int r = f >> 2, c8 = (f & 3) << 3;
            *(uint4*)(&As_u[r * (LDA_S/2) + (c8 >> 1)]) = rab[i];
        }
        #pragma unroll
        for (int i = 0; i < 2; i++) {
            int f = i * 256 + tid;
            int r = f >> 4;
            *(uint4*)(&Bs_u[r * (LDB_S/2) + (f & 15) * 4]) = rbb[i];
        }
        __syncthreads();

        if (k0 + 32 < K) { loadA(k0 + 32); loadB(k0 + 32); }

        #pragma unroll
        for (int ks = 0; ks < 2; ks++) {
            uint32_t aregs[4][4], bregs[2][4];
            #pragma unroll
            for (int mt = 0; mt < 4; mt++) {
                uint32_t addr = asBase +
                    ((wm*64 + mt*16 + (lane & 15)) * LDA_S + ks*16 + (lane >> 4)*8) * 2;
                ldsm4(aregs[mt], addr);
            }
            #pragma unroll
            for (int j = 0; j < 2; j++) {
                uint32_t addr = bsBase +
                    ((ks*16 + (lane & 15)) * LDB_S + wn*32 + j*16 + (lane >> 4)*8) * 2;
                ldsm4t(bregs[j], addr);
            }
            #pragma unroll
            for (int mt = 0; mt < 4; mt++)
                #pragma unroll
                for (int nt = 0; nt < 4; nt++)
                    mma16816(acc[mt][nt], aregs[mt], &bregs[nt >> 1][(nt & 1) * 2]);
        }
        __syncthreads();
    }

    float bc[4][2];
    #pragma unroll
    for (int nt = 0; nt < 4; nt++) {
        int col = nBase + wn*32 + nt*8 + (lane & 3)*2;
        bc[nt][0] = bias[col];
        bc[nt][1] = bias[col + 1];
    }
    #pragma unroll
    for (int mt = 0; mt < 4; mt++) {
        #pragma unroll
        for (int half = 0; half < 2; half++) {
            int row = mBase + wm*64 + mt*16 + (lane >> 2) + half*8;
            if (row >= M) continue;
            #pragma unroll
            for (int nt = 0; nt < 4; nt++) {
                int col = nBase + wn*32 + nt*8 + (lane & 3)*2;
                float v0 = acc[mt][nt][half*2]     + bc[nt][0];
                float v1 = acc[mt][nt][half*2 + 1] + bc[nt][1];
                if (RELU) { v0 = fmaxf(v0, 0.f); v1 = fmaxf(v1, 0.f); }
                if (RES) {
                    const float* rp = res + (size_t)row * Nc + col;
                    v0 += rp[0]; v1 += rp[1];
                }
                if (OBF) {
                    *(uint32_t*)((__nv_bfloat16*)Coutp + (size_t)row * Nc + col) = pk_bf2(v0, v1);
                } else {
                    *(float2*)((float*)Coutp + (size_t)row * Nc + col) = make_float2(v0, v1);
                }
            }
        }
    }
}

// ---------------- attention: bf16 in/out, fp32 math ----------------
__global__ void __launch_bounds__(128) attn_kernel(
    const __nv_bfloat16* __restrict__ Qb, const __nv_bfloat16* __restrict__ Kb,
    const __nv_bfloat16* __restrict__ Vb, const int* __restrict__ kmask,
    __nv_bfloat16* __restrict__ Ao)
{
    __shared__ float sQ[SQL][CDIM];
    __shared__ float sKV[SKL][132];
    __shared__ int   sM[SKL];
    const int w = blockIdx.x;
    const int tid = threadIdx.x;
    const int h = tid & 7;
    const int q = tid >> 3;

    #pragma unroll
    for (int i = 0; i < 2; i++) {
        int f = i * 128 + tid;
        int r = f >> 4, c8 = (f & 15) * 8;
        uint4 u = *(const uint4*)(Qb + (size_t)(w * SQL + r) * CDIM + c8);
        float2 a = bf2f(u.x), b = bf2f(u.y), c = bf2f(u.z), d = bf2f(u.w);
        sQ[r][c8+0]=a.x; sQ[r][c8+1]=a.y; sQ[r][c8+2]=b.x; sQ[r][c8+3]=b.y;
        sQ[r][c8+4]=c.x; sQ[r][c8+5]=c.y; sQ[r][c8+6]=d.x; sQ[r][c8+7]=d.y;
    }
    #pragma unroll
    for (int i = 0; i < 8; i++) {
        int f = i * 128 + tid;
        int r = f >> 4, c8 = (f & 15) * 8;
        uint4 u = *(const uint4*)(Kb + (size_t)(w * SKL + r) * CDIM + c8);
        float2 a = bf2f(u.x), b = bf2f(u.y), c = bf2f(u.z), d = bf2f(u.w);
        sKV[r][c8+0]=a.x; sKV[r][c8+1]=a.y; sKV[r][c8+2]=b.x; sKV[r][c8+3]=b.y;
        sKV[r][c8+4]=c.x; sKV[r][c8+5]=c.y; sKV[r][c8+6]=d.x; sKV[r][c8+7]=d.y;
    }
    if (tid < SKL) sM[tid] = kmask[w * SKL + tid];
    __syncthreads();

    float qreg[16];
    #pragma unroll
    for (int j = 0; j < 4; j++)
        *(float4*)(qreg + j * 4) = *(const float4*)(&sQ[q][h * 16 + j * 4]);

    float s[SKL];
    #pragma unroll
    for (int k = 0; k < SKL; k++) {
        float4 v0 = *(const float4*)(&sKV[k][h * 16 + 0]);
        float4 v1 = *(const float4*)(&sKV[k][h * 16 + 4]);
        float4 v2 = *(const float4*)(&sKV[k][h * 16 + 8]);
        float4 v3 = *(const float4*)(&sKV[k][h * 16 + 12]);
        float acc = qreg[0]*v0.x + qreg[1]*v0.y + qreg[2]*v0.z + qreg[3]*v0.w
                  + qreg[4]*v1.x + qreg[5]*v1.y + qreg[6]*v1.z + qreg[7]*v1.w
                  + qreg[8]*v2.x + qreg[9]*v2.y + qreg[10]*v2.z + qreg[11]*v2.w
                  + qreg[12]*v3.x + qreg[13]*v3.y + qreg[14]*v3.z + qreg[15]*v3.w;
        s[k] = sM[k] ? -1e9f : acc * 0.25f;
    }
    float mx = -1e30f;
    #pragma unroll
    for (int k = 0; k < SKL; k++) mx = fmaxf(mx, s[k]);
    float sum = 0.f;
    #pragma unroll
    for (int k = 0; k < SKL; k++) { float e = expf(s[k] - mx); s[k] = e; sum += e; }
    float inv = 1.f / sum;
    #pragma unroll
    for (int k = 0; k < SKL; k++) s[k] *= inv;

    __syncthreads();
    #pragma unroll
    for (int i = 0; i < 8; i++) {
        int f = i * 128 + tid;
        int r = f >> 4, c8 = (f & 15) * 8;
        uint4 u = *(const uint4*)(Vb + (size_t)(w * SKL + r) * CDIM + c8);
        float2 a = bf2f(u.x), b = bf2f(u.y), c = bf2f(u.z), d = bf2f(u.w);
        sKV[r][c8+0]=a.x; sKV[r][c8+1]=a.y; sKV[r][c8+2]=b.x; sKV[r][c8+3]=b.y;
        sKV[r][c8+4]=c.x; sKV[r][c8+5]=c.y; sKV[r][c8+6]=d.x; sKV[r][c8+7]=d.y;
    }
    __syncthreads();

    float4 o0 = make_float4(0,0,0,0), o1 = o0, o2 = o0, o3 = o0;
    #pragma unroll
    for (int k = 0; k < SKL; k++) {
        float p = s[k];
        float4 v0 = *(const float4*)(&sKV[k][h * 16 + 0]);
        float4 v1 = *(const float4*)(&sKV[k][h * 16 + 4]);
        float4 v2 = *(const float4*)(&sKV[k][h * 16 + 8]);
        float4 v3 = *(const float4*)(&sKV[k][h * 16 + 12]);
        o0.x = fmaf(p, v0.x, o0.x); o0.y = fmaf(p, v0.y, o0.y);
        o0.z = fmaf(p, v0.z, o0.z); o0.w = fmaf(p, v0.w, o0.w);
        o1.x = fmaf(p, v1.x, o1.x); o1.y = fmaf(p, v1.y, o1.y);
        o1.z = fmaf(p, v1.z, o1.z); o1.w = fmaf(p, v1.w, o1.w);
        o2.x = fmaf(p, v2.x, o2.x); o2.y = fmaf(p, v2.y, o2.y);
        o2.z = fmaf(p, v2.z, o2.z); o2.w = fmaf(p, v2.w, o2.w);
        o3.x = fmaf(p, v3.x, o3.x); o3.y = fmaf(p, v3.y, o3.y);
        o3.z = fmaf(p, v3.z, o3.z); o3.w = fmaf(p, v3.w, o3.w);
    }
    uint4 pa, pb;
    pa.x = pk_bf2(o0.x, o0.y); pa.y = pk_bf2(o0.z, o0.w);
    pa.z = pk_bf2(o1.x, o1.y); pa.w = pk_bf2(o1.z, o1.w);
    pb.x = pk_bf2(o2.x, o2.y); pb.y = pk_bf2(o2.z, o2.w);
    pb.z = pk_bf2(o3.x, o3.y); pb.w = pk_bf2(o3.z, o3.w);
    __nv_bfloat16* op = Ao + (size_t)(w * SQL + q) * CDIM + h * 16;
    *(uint4*)(op)     = pa;
    *(uint4*)(op + 8) = pb;
}

// ---------------- scatter-mean support ----------------
__global__ void clear_kernel(float* __restrict__ sums, float* __restrict__ cnt)
{
    int i = blockIdx.x * blockDim.x + threadIdx.x;
    if (i < NPTS * CDIM) sums[i] = 0.f;
    if (i < NPTS) cnt[i] = 0.f;
}

__global__ void scatter_kernel(const int* __restrict__ qind, const int* __restrict__ qmask,
                               const __nv_bfloat16* __restrict__ ob,
                               float* __restrict__ sums, float* __restrict__ cnt)
{
    int e = blockIdx.x * blockDim.x + threadIdx.x;
    if (e >= TQ * CDIM / 2) return;
    int t = e >> 6, c2 = (e & 63) * 2;
    if (qmask[t] == 0) {
        int idx = qind[t];
        float2 f = bf2f(*(const uint32_t*)(ob + (size_t)e * 2));
        atomicAdd(&sums[(size_t)idx * CDIM + c2],     f.x);
        atomicAdd(&sums[(size_t)idx * CDIM + c2 + 1], f.y);
        if (c2 == 0) atomicAdd(&cnt[idx], 1.0f);
    }
}

__global__ void resid_kernel(const float* __restrict__ feat, const float* __restrict__ sums,
                             const float* __restrict__ cnt, float* __restrict__ y)
{
    int e = blockIdx.x * blockDim.x + threadIdx.x;
    if (e >= NPTS * CDIM) return;
    int row = e >> 7;
    y[e] = feat[e] + sums[e] / fmaxf(cnt[row], 1.0f);
}

// ---------------- launch ----------------
extern "C" void kernel_launch(void* const* d_in, const int* in_sizes, int n_in,
                              void* d_out, int out_size)
{
    const float *features=nullptr, *q_pos=nullptr, *k_pos=nullptr;
    const float *ln1_g=nullptr, *ln1_b=nullptr, *pw1=nullptr, *pb1=nullptr;
    const float *pw2=nullptr, *pb2=nullptr;
    const float *wq=nullptr,*bq=nullptr,*wk=nullptr,*bk=nullptr,*wv=nullptr,*bv=nullptr,*wo=nullptr,*bo=nullptr;
    const float *ln2_g=nullptr,*ln2_b=nullptr,*fw1=nullptr,*fb1=nullptr,*fw2=nullptr,*fb2=nullptr;
    const int *q_ind=nullptr,*q_mask=nullptr,*k_ind=nullptr,*k_mask=nullptr;

    const float** slots128[11] = {&ln1_g,&ln1_b,&pb1,&pb2,&bq,&bk,&bv,&bo,&ln2_g,&ln2_b,&fb2};
    int c192=0, c768k=0, c16k=0, c64k=0, c128=0;
    for (int i = 0; i < n_in; i++) {
        int s = in_sizes[i];
        const void* p = d_in[i];
        if      (s == NPTS*CDIM)   features = (const float*)p;
        else if (s == NW*SQL*6)    q_pos = (const float*)p;
        else if (s == NW*SKL*6)    k_pos = (const float*)p;
        else if (s == NW*SQL)      { if (c192++ == 0) q_ind = (const int*)p; else q_mask = (const int*)p; }
        else if (s == NW*SKL)      { if (c768k++ == 0) k_ind = (const int*)p; else k_mask = (const int*)p; }
        else if (s == 6*CDIM)      pw1 = (const float*)p;
        else if (s == CDIM*CDIM) {
            const float* f = (const float*)p;
            switch (c16k++) { case 0: pw2=f; break; case 1: wq=f; break; case 2: wk=f; break;
                              case 3: wv=f; break; default: wo=f; break; }
        }
        else if (s == CDIM*FFD)    { if (c64k++ == 0) fw1 = (const float*)p; else fw2 = (const float*)p; }
        else if (s == FFD)         fb1 = (const float*)p;
        else if (s == CDIM)        { if (c128 < 11) *slots128[c128] = (const float*)p; c128++; }
    }

    float* arena = nullptr;
    cudaGetSymbolAddress((void**)&arena, g_arena);
    __nv_bfloat16* wb = nullptr;
    cudaGetSymbolAddress((void**)&wb, g_wbuf);

    __nv_bfloat16* hb  = (__nv_bfloat16*)(arena + O_HB);
    __nv_bfloat16* Qb  = (__nv_bfloat16*)(arena + O_QB);
    __nv_bfloat16* Kb  = (__nv_bfloat16*)(arena + O_KB);
    __nv_bfloat16* Vb  = (__nv_bfloat16*)(arena + O_VB);
    __nv_bfloat16* ao  = (__nv_bfloat16*)(arena + O_AOB);
    __nv_bfloat16* ob  = (__nv_bfloat16*)(arena + O_OBB);
    __nv_bfloat16* mid = (__nv_bfloat16*)(arena + O_MIDB);
    __nv_bfloat16* h2b = (__nv_bfloat16*)(arena + O_H2B);
    float* sums = arena + O_SUMS;
    float* cnt  = arena + O_CNT;
    float* yb   = arena + O_Y;
    float* out  = (float*)d_out;

    // 0. weights -> bf16 cache
    convert_w<<<832, 256>>>(pw2, wq, wk, wv, wo, fw1, fw2);
    // 1. pre-norm
    ln_kernel<<<(NPTS*32 + 255)/256, 256>>>(features, ln1_g, ln1_b, hb, NPTS);
    // 2. fused chains: posMLP+gather -> (x wq -> Q) | (x wk -> K, x wv -> V)
    gemm2_mma<1><<<TQ/128, 256>>>(q_pos, pw1, pb1, wb + W_PW2, pb2, q_ind, hb,
                                  wb + W_WQ, bq, Qb, nullptr, nullptr, nullptr);
    gemm2_mma<2><<<TK/128, 256>>>(k_pos, pw1, pb1, wb + W_PW2, pb2, k_ind, hb,
                                  wb + W_WK, bk, Kb, wb + W_WV, bv, Vb);
    // 3. windowed attention
    attn_kernel<<<NW, 128>>>(Qb, Kb, Vb, k_mask, ao);
    // 4. output projection
    gemm_mma<false,false,true><<<dim3(TQ/128, 1), 256>>>(ao, wb + W_WO, bo, ob, TQ, CDIM, CDIM, nullptr);
    // 5. masked scatter-mean + residual
    clear_kernel<<<(NPTS*CDIM + 255)/256, 256>>>(sums, cnt);
    scatter_kernel<<<(TQ*CDIM/2 + 255)/256, 256>>>(q_ind, q_mask, ob, sums, cnt);
    resid_kernel<<<(NPTS*CDIM + 255)/256, 256>>>(features, sums, cnt, yb);
    // 6. FFN with pre-norm + residual
    ln_kernel<<<(NPTS*32 + 255)/256, 256>>>(yb, ln2_g, ln2_b, h2b, NPTS);
    gemm_mma<true,false,true><<<dim3((NPTS + 127)/128, FFD/128), 256>>>(h2b, wb + W_FW1, fb1, mid, NPTS, CDIM, FFD, nullptr);
    gemm_mma<false,true,false><<<dim3((NPTS + 127)/128, 1), 256>>>(mid, wb + W_FW2, fb2, out, NPTS, FFD, CDIM, yb);
}

// round 7
// speedup vs baseline: 2.1479x; 1.0009x over previous
#include <cuda_runtime.h>
#include <cuda_bf16.h>
#include <cstddef>
#include <cstdint>

#define NPTS 120000
#define CDIM 128
#define NW   12000
#define SQL  16
#define SKL  64
#define FFD  512
#define TQ   (NW*SQL)   /* 192000 */
#define TK   (NW*SKL)   /* 768000 */

// ---------------- arena (float units) ----------------
#define O_HB   ((size_t)0)                        /* h    bf16  -> 7.68M fl   */
#define O_QB   ((size_t)7680000)                  /* Q    bf16  -> 12.288M fl */
#define O_KB   ((size_t)19968000)                 /* K    bf16  -> 49.152M fl */
#define O_VB   ((size_t)69120000)                 /* V    bf16  -> 49.152M fl */
#define O_AOB  ((size_t)118272000)                /* ao   bf16  -> 12.288M fl */
#define ARENA_FLOATS ((size_t)130560000)          /* 522 MB */

#define O_OBB  O_KB                               /* ob  bf16 (K dead)        */
#define O_MIDB (O_KB + (size_t)12288000)          /* mid bf16 (30.72M fl)     */
#define O_SUMS O_VB                               /* sums fp32 (V dead)       */
#define O_CNT  (O_VB + (size_t)15360000)          /* cnt fp32                 */
#define O_Y    (O_VB + (size_t)15480064)          /* y   fp32                 */
#define O_H2B  O_QB                               /* h2  bf16 (Q dead)        */

__device__ float g_arena[ARENA_FLOATS];

// bf16 weight cache: [pw2|wq|wk|wv|wo|fw1|fw2]
#define W_PW2 0
#define W_WQ  16384
#define W_WK  32768
#define W_WV  49152
#define W_WO  65536
#define W_FW1 81920
#define W_FW2 147456
__device__ __nv_bfloat16 g_wbuf[212992];

// ---------------- PTX helpers ----------------
__device__ __forceinline__ uint32_t pk_bf2(float lo, float hi) {
    uint32_t r;
    asm("cvt.rn.bf16x2.f32 %0, %1, %2;" : "=r"(r) : "f"(hi), "f"(lo));
    return r;
}
__device__ __forceinline__ float2 bf2f(uint32_t u) {
    return __bfloat1622float2(*(__nv_bfloat162*)&u);
}
__device__ __forceinline__ void ldsm4(uint32_t* r, uint32_t addr) {
    asm volatile("ldmatrix.sync.aligned.m8n8.x4.shared.b16 {%0,%1,%2,%3}, [%4];"
        : "=r"(r[0]), "=r"(r[1]), "=r"(r[2]), "=r"(r[3]) : "r"(addr));
}
__device__ __forceinline__ void ldsm4t(uint32_t* r, uint32_t addr) {
    asm volatile("ldmatrix.sync.aligned.m8n8.x4.trans.shared.b16 {%0,%1,%2,%3}, [%4];"
        : "=r"(r[0]), "=r"(r[1]), "=r"(r[2]), "=r"(r[3]) : "r"(addr));
}
__device__ __forceinline__ void mma16816(float* d, const uint32_t* a, const uint32_t* b) {
    asm volatile("mma.sync.aligned.m16n8k16.row.col.f32.bf16.bf16.f32 "
        "{%0,%1,%2,%3}, {%4,%5,%6,%7}, {%8,%9}, {%0,%1,%2,%3};"
        : "+f"(d[0]), "+f"(d[1]), "+f"(d[2]), "+f"(d[3])
        : "r"(a[0]), "r"(a[1]), "r"(a[2]), "r"(a[3]), "r"(b[0]), "r"(b[1]));
}

// ---------------- weight convert (once per graph replay; deterministic) ----------------
__global__ void convert_w(const float* __restrict__ pw2, const float* __restrict__ wq,
                          const float* __restrict__ wk,  const float* __restrict__ wv,
                          const float* __restrict__ wo,  const float* __restrict__ fw1,
                          const float* __restrict__ fw2)
{
    int b = blockIdx.x, t = threadIdx.x;
    const float* src; int base, idx;
    if      (b <  64) { src = pw2; base = W_PW2; idx = b*256 + t; }
    else if (b < 128) { src = wq;  base = W_WQ;  idx = (b-64)*256 + t; }
    else if (b < 192) { src = wk;  base = W_WK;  idx = (b-128)*256 + t; }
    else if (b < 256) { src = wv;  base = W_WV;  idx = (b-192)*256 + t; }
    else if (b < 320) { src = wo;  base = W_WO;  idx = (b-256)*256 + t; }
    else if (b < 576) { src = fw1; base = W_FW1; idx = (b-320)*256 + t; }
    else              { src = fw2; base = W_FW2; idx = (b-576)*256 + t; }
    g_wbuf[base + idx] = __float2bfloat16(src[idx]);
}

// ---------------- LayerNorm (fp32 in, bf16 out) ----------------
__global__ void ln_kernel(const float* __restrict__ x, const float* __restrict__ g,
                          const float* __restrict__ b, __nv_bfloat16* __restrict__ out, int rows)
{
    int gid  = blockIdx.x * blockDim.x + threadIdx.x;
    int row  = gid >> 5;
    int lane = gid & 31;
    if (row >= rows) return;
    float4 v = *((const float4*)(x + (size_t)row * CDIM) + lane);
    float s  = v.x + v.y + v.z + v.w;
    float sq = v.x*v.x + v.y*v.y + v.z*v.z + v.w*v.w;
    #pragma unroll
    for (int o = 16; o > 0; o >>= 1) {
        s  += __shfl_xor_sync(0xffffffffu, s,  o);
        sq += __shfl_xor_sync(0xffffffffu, sq, o);
    }
    float m   = s * (1.0f / CDIM);
    float var = sq * (1.0f / CDIM) - m * m;
    float rs  = rsqrtf(var + 1e-5f);
    float4 gg = ((const float4*)g)[lane];
    float4 bb = ((const float4*)b)[lane];
    uint2 o2;
    o2.x = pk_bf2((v.x - m) * rs * gg.x + bb.x, (v.y - m) * rs * gg.y + bb.y);
    o2.y = pk_bf2((v.z - m) * rs * gg.z + bb.z, (v.w - m) * rs * gg.w + bb.w);
    *(uint2*)(out + (size_t)row * CDIM + lane * 4) = o2;
}

// ================= fused chain GEMM =================
// Phase 1: C1 = relu(pos@w1 + b1)@pw2 + pb2, relu, + h[gidx]   (kept in SMEM, bf16)
// Phase 2: out_j = C1 @ w2_j + b2_j   for j < NOUT
// BM=128, BN=128, BK=32, 256 threads (8 warps: 2m x 4n)
#define LDA_S 40    /* phase-1 As: bf16/row (32+8) */
#define LDB_S 136   /* Bs & C1: bf16/row (128+8)   */

template<int NOUT>
__global__ void __launch_bounds__(256) gemm2_mma(
    const float* __restrict__ pos,
    const float* __restrict__ pw1, const float* __restrict__ pb1,
    const __nv_bfloat16* __restrict__ pw2bf, const float* __restrict__ pb2,
    const int* __restrict__ gidx, const __nv_bfloat16* __restrict__ gsrc,
    const __nv_bfloat16* __restrict__ w2a, const float* __restrict__ b2a, __nv_bfloat16* __restrict__ outa,
    const __nv_bfloat16* __restrict__ w2b, const float* __restrict__ b2b, __nv_bfloat16* __restrict__ outb)
{
    __shared__ __align__(16) char sbuf[47104];
    uint32_t* C1_u = (uint32_t*)sbuf;             // 128 x (LDB_S/2), phase 2 A source
    uint32_t* As_u = (uint32_t*)sbuf;             // 128 x (LDA_S/2), phase-1 only (overlaps C1)
    uint32_t* Bs_u = (uint32_t*)(sbuf + 34816);   // 32 x (LDB_S/2)
    float*    Wall = (float*)(sbuf + 43520);      // w1(6x128)+b1(128)

    const int tid = threadIdx.x, lane = tid & 31, wid = tid >> 5;
    const int wm = wid & 1, wn = wid >> 1;
    const int mBase = blockIdx.x * 128;

    float preg[6];
    {
        const float* pp = pos + (size_t)(mBase + (tid >> 1)) * 6;
        #pragma unroll
        for (int i = 0; i < 6; i++) preg[i] = pp[i];
    }
    if (tid < 192) ((float4*)Wall)[tid] = ((const float4*)pw1)[tid];
    if (tid < 32)  ((float4*)(Wall + 6*CDIM))[tid] = ((const float4*)pb1)[tid];
    __syncthreads();

    uint32_t asB = (uint32_t)__cvta_generic_to_shared(As_u);
    uint32_t bsB = (uint32_t)__cvta_generic_to_shared(Bs_u);

    float acc[4][4][4];
    #pragma unroll
    for (int mt = 0; mt < 4; mt++)
        #pragma unroll
        for (int nt = 0; nt < 4; nt++)
            #pragma unroll
            for (int i = 0; i < 4; i++) acc[mt][nt][i] = 0.f;

    uint4 rbb[2];
    auto loadBW = [&](const __nv_bfloat16* W, int k0) {
        #pragma unroll
        for (int i = 0; i < 2; i++) {
            int f = i * 256 + tid;
            int r = f >> 4, c8 = (f & 15) * 8;
            rbb[i] = *(const uint4*)(W + (size_t)(k0 + r) * CDIM + c8);
        }
    };
    auto storeBs = [&]() {
        #pragma unroll
        for (int i = 0; i < 2; i++) {
            int f = i * 256 + tid;
            int r = f >> 4;
            *(uint4*)&Bs_u[r * (LDB_S/2) + (f & 15) * 4] = rbb[i];
        }
    };

    // ---------- phase 1 ----------
    loadBW(pw2bf, 0);
    for (int k0 = 0; k0 < 128; k0 += 32) {
        {
            const int row = tid >> 1;
            const int cb  = (tid & 1) * 16;
            #pragma unroll
            for (int cc = 0; cc < 16; cc += 2) {
                int kc = k0 + cb + cc;
                float v0 = Wall[6*CDIM + kc];
                float v1 = Wall[6*CDIM + kc + 1];
                #pragma unroll
                for (int i = 0; i < 6; i++) {
                    v0 = fmaf(preg[i], Wall[i*CDIM + kc],     v0);
                    v1 = fmaf(preg[i], Wall[i*CDIM + kc + 1], v1);
                }
                As_u[row * (LDA_S/2) + ((cb + cc) >> 1)] = pk_bf2(fmaxf(v0, 0.f), fmaxf(v1, 0.f));
            }
        }
        storeBs();
        __syncthreads();
        if (k0 + 32 < 128) loadBW(pw2bf, k0 + 32);
        #pragma unroll
        for (int ks = 0; ks < 2; ks++) {
            uint32_t aregs[4][4], bregs[2][4];
            #pragma unroll
            for (int mt = 0; mt < 4; mt++) {
                uint32_t addr = asB +
                    ((wm*64 + mt*16 + (lane & 15)) * LDA_S + ks*16 + (lane >> 4)*8) * 2;
                ldsm4(aregs[mt], addr);
            }
            #pragma unroll
            for (int j = 0; j < 2; j++) {
                uint32_t addr = bsB +
                    ((ks*16 + (lane & 15)) * LDB_S + wn*32 + j*16 + (lane >> 4)*8) * 2;
                ldsm4t(bregs[j], addr);
            }
            #pragma unroll
            for (int mt = 0; mt < 4; mt++)
                #pragma unroll
                for (int nt = 0; nt < 4; nt++)
                    mma16816(acc[mt][nt], aregs[mt], &bregs[nt >> 1][(nt & 1) * 2]);
        }
        __syncthreads();
    }

    // phase-1 epilogue -> C1 smem (overlays As; all As reads done)
    {
        float bc[4][2];
        #pragma unroll
        for (int nt = 0; nt < 4; nt++) {
            int col = wn*32 + nt*8 + (lane & 3)*2;
            bc[nt][0] = pb2[col];
            bc[nt][1] = pb2[col + 1];
        }
        #pragma unroll
        for (int mt = 0; mt < 4; mt++) {
            #pragma unroll
            for (int half = 0; half < 2; half++) {
                int rl = wm*64 + mt*16 + (lane >> 2) + half*8;
                int gi = gidx[mBase + rl];
                #pragma unroll
                for (int nt = 0; nt < 4; nt++) {
                    int col = wn*32 + nt*8 + (lane & 3)*2;
                    float v0 = fmaxf(acc[mt][nt][half*2]     + bc[nt][0], 0.f);
                    float v1 = fmaxf(acc[mt][nt][half*2 + 1] + bc[nt][1], 0.f);
                    float2 g2 = bf2f(*(const uint32_t*)(gsrc + (size_t)gi * CDIM + col));
                    v0 += g2.x; v1 += g2.y;
                    C1_u[rl * (LDB_S/2) + (col >> 1)] = pk_bf2(v0, v1);
                }
            }
        }
    }
    __syncthreads();

    // ---------- phase 2: out_j = C1 @ w2_j + b2_j ----------
    #pragma unroll
    for (int j = 0; j < NOUT; j++) {
        const __nv_bfloat16* W = (j == 0) ? w2a : w2b;
        const float* b2        = (j == 0) ? b2a : b2b;
        __nv_bfloat16* outp    = (j == 0) ? outa : outb;

        #pragma unroll
        for (int mt = 0; mt < 4; mt++)
            #pragma unroll
            for (int nt = 0; nt < 4; nt++)
                #pragma unroll
                for (int i = 0; i < 4; i++) acc[mt][nt][i] = 0.f;

        loadBW(W, 0);
        for (int k0 = 0; k0 < 128; k0 += 32) {
            __syncthreads();                 // Bs consumers from previous chunk done
            storeBs();
            __syncthreads();
            if (k0 + 32 < 128) loadBW(W, k0 + 32);
            #pragma unroll
            for (int ks = 0; ks < 2; ks++) {
                uint32_t aregs[4][4], bregs[2][4];
                #pragma unroll
                for (int mt = 0; mt < 4; mt++) {
                    uint32_t addr = asB +
                        ((wm*64 + mt*16 + (lane & 15)) * LDB_S + k0 + ks*16 + (lane >> 4)*8) * 2;
                    ldsm4(aregs[mt], addr);
                }
                #pragma unroll
                for (int jj = 0; jj < 2; jj++) {
                    uint32_t addr = bsB +
                        ((ks*16 + (lane & 15)) * LDB_S + wn*32 + jj*16 + (lane >> 4)*8) * 2;
                    ldsm4t(bregs[jj], addr);
                }
                #pragma unroll
                for (int mt = 0; mt < 4; mt++)
                    #pragma unroll
                    for (int nt = 0; nt < 4; nt++)
                        mma16816(acc[mt][nt], aregs[mt], &bregs[nt >> 1][(nt & 1) * 2]);
            }
        }

        float bc[4][2];
        #pragma unroll
        for (int nt = 0; nt < 4; nt++) {
            int col = wn*32 + nt*8 + (lane & 3)*2;
            bc[nt][0] = b2[col];
            bc[nt][1] = b2[col + 1];
        }
        #pragma unroll
        for (int mt = 0; mt < 4; mt++) {
            #pragma unroll
            for (int half = 0; half < 2; half++) {
                int rl = wm*64 + mt*16 + (lane >> 2) + half*8;
                #pragma unroll
                for (int nt = 0; nt < 4; nt++) {
                    int col = wn*32 + nt*8 + (lane & 3)*2;
                    float v0 = acc[mt][nt][half*2]     + bc[nt][0];
                    float v1 = acc[mt][nt][half*2 + 1] + bc[nt][1];
                    *(uint32_t*)(outp + (size_t)(mBase + rl) * CDIM + col) = pk_bf2(v0, v1);
                }
            }
        }
    }
}

// ---------------- plain bf16 GEMM (bf16 A, bf16 B) ----------------
template<bool RELU, bool RES, bool OBF>
__global__ void __launch_bounds__(256) gemm_mma(
    const __nv_bfloat16* __restrict__ A, const __nv_bfloat16* __restrict__ B,
    const float* __restrict__ bias, void* __restrict__ Coutp,
    int M, int K, int Nc, const float* __restrict__ res)
{
    __shared__ uint32_t As_u[128 * (LDA_S/2)];
    __shared__ uint32_t Bs_u[32 * (LDB_S/2)];

    const int tid  = threadIdx.x;
    const int lane = tid & 31;
    const int wid  = tid >> 5;
    const int wm   = wid & 1;
    const int wn   = wid >> 1;
    const int mBase = blockIdx.x * 128;
    const int nBase = blockIdx.y * 128;

    uint32_t asBase = (uint32_t)__cvta_generic_to_shared(As_u);
    uint32_t bsBase = (uint32_t)__cvta_generic_to_shared(Bs_u);

    float acc[4][4][4];
    #pragma unroll
    for (int mt = 0; mt < 4; mt++)
        #pragma unroll
        for (int nt = 0; nt < 4; nt++)
            #pragma unroll
            for (int i = 0; i < 4; i++) acc[mt][nt][i] = 0.f;

    uint4 rab[2], rbb[2];
    auto loadA = [&](int k0) {
        #pragma unroll
        for (int i = 0; i < 2; i++) {
            int f = i * 256 + tid;
            int r = f >> 2, c8 = (f & 3) << 3;
            int grow = mBase + r;
            rab[i] = (grow < M) ? *(const uint4*)(A + (size_t)grow * K + k0 + c8)
                                : make_uint4(0u, 0u, 0u, 0u);
        }
    };
    auto loadB = [&](int k0) {
        #pragma unroll
        for (int i = 0; i < 2; i++) {
            int f = i * 256 + tid;
            int r = f >> 4, c8 = (f & 15) * 8;
            rbb[i] = *(const uint4*)(B + (size_t)(k0 + r) * Nc + nBase + c8);
        }
    };

    loadA(0);
    loadB(0);

    for (int k0 = 0; k0 < K; k0 += 32) {
        #pragma unroll
        for (int i = 0; i < 2; i++) {
            int f = i * 256 + tid;
            int r = f >> 2, c8 = (f & 3) << 3;
            *(uint4*)(&As_u[r * (LDA_S/2) + (c8 >> 1)]) = rab[i];
        }
        #pragma unroll
        for (int i = 0; i < 2; i++) {
            int f = i * 256 + tid;
            int r = f >> 4;
            *(uint4*)(&Bs_u[r * (LDB_S/2) + (f & 15) * 4]) = rbb[i];
        }
        __syncthreads();

        if (k0 + 32 < K) { loadA(k0 + 32); loadB(k0 + 32); }

        #pragma unroll
        for (int ks = 0; ks < 2; ks++) {
            uint32_t aregs[4][4], bregs[2][4];
            #pragma unroll
            for (int mt = 0; mt < 4; mt++) {
                uint32_t addr = asBase +
                    ((wm*64 + mt*16 + (lane & 15)) * LDA_S + ks*16 + (lane >> 4)*8) * 2;
                ldsm4(aregs[mt], addr);
            }
            #pragma unroll
            for (int j = 0; j < 2; j++) {
                uint32_t addr = bsBase +
                    ((ks*16 + (lane & 15)) * LDB_S + wn*32 + j*16 + (lane >> 4)*8) * 2;
                ldsm4t(bregs[j], addr);
            }
            #pragma unroll
            for (int mt = 0; mt < 4; mt++)
                #pragma unroll
                for (int nt = 0; nt < 4; nt++)
                    mma16816(acc[mt][nt], aregs[mt], &bregs[nt >> 1][(nt & 1) * 2]);
        }
        __syncthreads();
    }

    float bc[4][2];
    #pragma unroll
    for (int nt = 0; nt < 4; nt++) {
        int col = nBase + wn*32 + nt*8 + (lane & 3)*2;
        bc[nt][0] = bias[col];
        bc[nt][1] = bias[col + 1];
    }
    #pragma unroll
    for (int mt = 0; mt < 4; mt++) {
        #pragma unroll
        for (int half = 0; half < 2; half++) {
            int row = mBase + wm*64 + mt*16 + (lane >> 2) + half*8;
            if (row >= M) continue;
            #pragma unroll
            for (int nt = 0; nt < 4; nt++) {
                int col = nBase + wn*32 + nt*8 + (lane & 3)*2;
                float v0 = acc[mt][nt][half*2]     + bc[nt][0];
                float v1 = acc[mt][nt][half*2 + 1] + bc[nt][1];
                if (RELU) { v0 = fmaxf(v0, 0.f); v1 = fmaxf(v1, 0.f); }
                if (RES) {
                    const float* rp = res + (size_t)row * Nc + col;
                    v0 += rp[0]; v1 += rp[1];
                }
                if (OBF) {
                    *(uint32_t*)((__nv_bfloat16*)Coutp + (size_t)row * Nc + col) = pk_bf2(v0, v1);
                } else {
                    *(float2*)((float*)Coutp + (size_t)row * Nc + col) = make_float2(v0, v1);
                }
            }
        }
    }
}

// ---------------- attention: bf16 in/out, fp32 math ----------------
__global__ void __launch_bounds__(128) attn_kernel(
    const __nv_bfloat16* __restrict__ Qb, const __nv_bfloat16* __restrict__ Kb,
    const __nv_bfloat16* __restrict__ Vb, const int* __restrict__ kmask,
    __nv_bfloat16* __restrict__ Ao)
{
    __shared__ float sQ[SQL][CDIM];
    __shared__ float sKV[SKL][132];
    __shared__ int   sM[SKL];
    const int w = blockIdx.x;
    const int tid = threadIdx.x;
    const int h = tid & 7;
    const int q = tid >> 3;

    #pragma unroll
    for (int i = 0; i < 2; i++) {
        int f = i * 128 + tid;
        int r = f >> 4, c8 = (f & 15) * 8;
        uint4 u = *(const uint4*)(Qb + (size_t)(w * SQL + r) * CDIM + c8);
        float2 a = bf2f(u.x), b = bf2f(u.y), c = bf2f(u.z), d = bf2f(u.w);
        sQ[r][c8+0]=a.x; sQ[r][c8+1]=a.y; sQ[r][c8+2]=b.x; sQ[r][c8+3]=b.y;
        sQ[r][c8+4]=c.x; sQ[r][c8+5]=c.y; sQ[r][c8+6]=d.x; sQ[r][c8+7]=d.y;
    }
    #pragma unroll
    for (int i = 0; i < 8; i++) {
        int f = i * 128 + tid;
        int r = f >> 4, c8 = (f & 15) * 8;
        uint4 u = *(const uint4*)(Kb + (size_t)(w * SKL + r) * CDIM + c8);
        float2 a = bf2f(u.x), b = bf2f(u.y), c = bf2f(u.z), d = bf2f(u.w);
        sKV[r][c8+0]=a.x; sKV[r][c8+1]=a.y; sKV[r][c8+2]=b.x; sKV[r][c8+3]=b.y;
        sKV[r][c8+4]=c.x; sKV[r][c8+5]=c.y; sKV[r][c8+6]=d.x; sKV[r][c8+7]=d.y;
    }
    if (tid < SKL) sM[tid] = kmask[w * SKL + tid];
    __syncthreads();

    float qreg[16];
    #pragma unroll
    for (int j = 0; j < 4; j++)
        *(float4*)(qreg + j * 4) = *(const float4*)(&sQ[q][h * 16 + j * 4]);

    float s[SKL];
    #pragma unroll
    for (int k = 0; k < SKL; k++) {
        float4 v0 = *(const float4*)(&sKV[k][h * 16 + 0]);
        float4 v1 = *(const float4*)(&sKV[k][h * 16 + 4]);
        float4 v2 = *(const float4*)(&sKV[k][h * 16 + 8]);
        float4 v3 = *(const float4*)(&sKV[k][h * 16 + 12]);
        float acc = qreg[0]*v0.x + qreg[1]*v0.y + qreg[2]*v0.z + qreg[3]*v0.w
                  + qreg[4]*v1.x + qreg[5]*v1.y + qreg[6]*v1.z + qreg[7]*v1.w
                  + qreg[8]*v2.x + qreg[9]*v2.y + qreg[10]*v2.z + qreg[11]*v2.w
                  + qreg[12]*v3.x + qreg[13]*v3.y + qreg[14]*v3.z + qreg[15]*v3.w;
        s[k] = sM[k] ? -1e9f : acc * 0.25f;
    }
    float mx = -1e30f;
    #pragma unroll
    for (int k = 0; k < SKL; k++) mx = fmaxf(mx, s[k]);
    float sum = 0.f;
    #pragma unroll
    for (int k = 0; k < SKL; k++) { float e = expf(s[k] - mx); s[k] = e; sum += e; }
    float inv = 1.f / sum;
    #pragma unroll
    for (int k = 0; k < SKL; k++) s[k] *= inv;

    __syncthreads();
    #pragma unroll
    for (int i = 0; i < 8; i++) {
        int f = i * 128 + tid;
        int r = f >> 4, c8 = (f & 15) * 8;
        uint4 u = *(const uint4*)(Vb + (size_t)(w * SKL + r) * CDIM + c8);
        float2 a = bf2f(u.x), b = bf2f(u.y), c = bf2f(u.z), d = bf2f(u.w);
        sKV[r][c8+0]=a.x; sKV[r][c8+1]=a.y; sKV[r][c8+2]=b.x; sKV[r][c8+3]=b.y;
        sKV[r][c8+4]=c.x; sKV[r][c8+5]=c.y; sKV[r][c8+6]=d.x; sKV[r][c8+7]=d.y;
    }
    __syncthreads();

    float4 o0 = make_float4(0,0,0,0), o1 = o0, o2 = o0, o3 = o0;
    #pragma unroll
    for (int k = 0; k < SKL; k++) {
        float p = s[k];
        float4 v0 = *(const float4*)(&sKV[k][h * 16 + 0]);
        float4 v1 = *(const float4*)(&sKV[k][h * 16 + 4]);
        float4 v2 = *(const float4*)(&sKV[k][h * 16 + 8]);
        float4 v3 = *(const float4*)(&sKV[k][h * 16 + 12]);
        o0.x = fmaf(p, v0.x, o0.x); o0.y = fmaf(p, v0.y, o0.y);
        o0.z = fmaf(p, v0.z, o0.z); o0.w = fmaf(p, v0.w, o0.w);
        o1.x = fmaf(p, v1.x, o1.x); o1.y = fmaf(p, v1.y, o1.y);
        o1.z = fmaf(p, v1.z, o1.z); o1.w = fmaf(p, v1.w, o1.w);
        o2.x = fmaf(p, v2.x, o2.x); o2.y = fmaf(p, v2.y, o2.y);
        o2.z = fmaf(p, v2.z, o2.z); o2.w = fmaf(p, v2.w, o2.w);
        o3.x = fmaf(p, v3.x, o3.x); o3.y = fmaf(p, v3.y, o3.y);
        o3.z = fmaf(p, v3.z, o3.z); o3.w = fmaf(p, v3.w, o3.w);
    }
    uint4 pa, pb;
    pa.x = pk_bf2(o0.x, o0.y); pa.y = pk_bf2(o0.z, o0.w);
    pa.z = pk_bf2(o1.x, o1.y); pa.w = pk_bf2(o1.z, o1.w);
    pb.x = pk_bf2(o2.x, o2.y); pb.y = pk_bf2(o2.z, o2.w);
    pb.z = pk_bf2(o3.x, o3.y); pb.w = pk_bf2(o3.z, o3.w);
    __nv_bfloat16* op = Ao + (size_t)(w * SQL + q) * CDIM + h * 16;
    *(uint4*)(op)     = pa;
    *(uint4*)(op + 8) = pb;
}

// ---------------- scatter-mean support ----------------
__global__ void clear_kernel(float* __restrict__ sums, float* __restrict__ cnt)
{
    int i = blockIdx.x * blockDim.x + threadIdx.x;
    if (i < NPTS * CDIM) sums[i] = 0.f;
    if (i < NPTS) cnt[i] = 0.f;
}

__global__ void scatter_kernel(const int* __restrict__ qind, const int* __restrict__ qmask,
                               const __nv_bfloat16* __restrict__ ob,
                               float* __restrict__ sums, float* __restrict__ cnt)
{
    int e = blockIdx.x * blockDim.x + threadIdx.x;
    if (e >= TQ * CDIM / 2) return;
    int t = e >> 6, c2 = (e & 63) * 2;
    if (qmask[t] == 0) {
        int idx = qind[t];
        float2 f = bf2f(*(const uint32_t*)(ob + (size_t)e * 2));
        atomicAdd(&sums[(size_t)idx * CDIM + c2],     f.x);
        atomicAdd(&sums[(size_t)idx * CDIM + c2 + 1], f.y);
        if (c2 == 0) atomicAdd(&cnt[idx], 1.0f);
    }
}

__global__ void resid_kernel(const float* __restrict__ feat, const float* __restrict__ sums,
                             const float* __restrict__ cnt, float* __restrict__ y)
{
    int e = blockIdx.x * blockDim.x + threadIdx.x;
    if (e >= NPTS * CDIM) return;
    int row = e >> 7;
    y[e] = feat[e] + sums[e] / fmaxf(cnt[row], 1.0f);
}

// ---------------- launch ----------------
extern "C" void kernel_launch(void* const* d_in, const int* in_sizes, int n_in,
                              void* d_out, int out_size)
{
    const float *features=nullptr, *q_pos=nullptr, *k_pos=nullptr;
    const float *ln1_g=nullptr, *ln1_b=nullptr, *pw1=nullptr, *pb1=nullptr;
    const float *pw2=nullptr, *pb2=nullptr;
    const float *wq=nullptr,*bq=nullptr,*wk=nullptr,*bk=nullptr,*wv=nullptr,*bv=nullptr,*wo=nullptr,*bo=nullptr;
    const float *ln2_g=nullptr,*ln2_b=nullptr,*fw1=nullptr,*fb1=nullptr,*fw2=nullptr,*fb2=nullptr;
    const int *q_ind=nullptr,*q_mask=nullptr,*k_ind=nullptr,*k_mask=nullptr;

    const float** slots128[11] = {&ln1_g,&ln1_b,&pb1,&pb2,&bq,&bk,&bv,&bo,&ln2_g,&ln2_b,&fb2};
    int c192=0, c768k=0, c16k=0, c64k=0, c128=0;
    for (int i = 0; i < n_in; i++) {
        int s = in_sizes[i];
        const void* p = d_in[i];
        if      (s == NPTS*CDIM)   features = (const float*)p;
        else if (s == NW*SQL*6)    q_pos = (const float*)p;
        else if (s == NW*SKL*6)    k_pos = (const float*)p;
        else if (s == NW*SQL)      { if (c192++ == 0) q_ind = (const int*)p; else q_mask = (const int*)p; }
        else if (s == NW*SKL)      { if (c768k++ == 0) k_ind = (const int*)p; else k_mask = (const int*)p; }
        else if (s == 6*CDIM)      pw1 = (const float*)p;
        else if (s == CDIM*CDIM) {
            const float* f = (const float*)p;
            switch (c16k++) { case 0: pw2=f; break; case 1: wq=f; break; case 2: wk=f; break;
                              case 3: wv=f; break; default: wo=f; break; }
        }
        else if (s == CDIM*FFD)    { if (c64k++ == 0) fw1 = (const float*)p; else fw2 = (const float*)p; }
        else if (s == FFD)         fb1 = (const float*)p;
        else if (s == CDIM)        { if (c128 < 11) *slots128[c128] = (const float*)p; c128++; }
    }

    float* arena = nullptr;
    cudaGetSymbolAddress((void**)&arena, g_arena);
    __nv_bfloat16* wb = nullptr;
    cudaGetSymbolAddress((void**)&wb, g_wbuf);

    __nv_bfloat16* hb  = (__nv_bfloat16*)(arena + O_HB);
    __nv_bfloat16* Qb  = (__nv_bfloat16*)(arena + O_QB);
    __nv_bfloat16* Kb  = (__nv_bfloat16*)(arena + O_KB);
    __nv_bfloat16* Vb  = (__nv_bfloat16*)(arena + O_VB);
    __nv_bfloat16* ao  = (__nv_bfloat16*)(arena + O_AOB);
    __nv_bfloat16* ob  = (__nv_bfloat16*)(arena + O_OBB);
    __nv_bfloat16* mid = (__nv_bfloat16*)(arena + O_MIDB);
    __nv_bfloat16* h2b = (__nv_bfloat16*)(arena + O_H2B);
    float* sums = arena + O_SUMS;
    float* cnt  = arena + O_CNT;
    float* yb   = arena + O_Y;
    float* out  = (float*)d_out;

    // 0. weights -> bf16 cache
    convert_w<<<832, 256>>>(pw2, wq, wk, wv, wo, fw1, fw2);
    // 1. pre-norm
    ln_kernel<<<(NPTS*32 + 255)/256, 256>>>(features, ln1_g, ln1_b, hb, NPTS);
    // 2. fused chains: posMLP+gather -> (x wq -> Q) | (x wk -> K, x wv -> V)
    gemm2_mma<1><<<TQ/128, 256>>>(q_pos, pw1, pb1, wb + W_PW2, pb2, q_ind, hb,
                                  wb + W_WQ, bq, Qb, nullptr, nullptr, nullptr);
    gemm2_mma<2><<<TK/128, 256>>>(k_pos, pw1, pb1, wb + W_PW2, pb2, k_ind, hb,
                                  wb + W_WK, bk, Kb, wb + W_WV, bv, Vb);
    // 3. windowed attention
    attn_kernel<<<NW, 128>>>(Qb, Kb, Vb, k_mask, ao);
    // 4. output projection
    gemm_mma<false,false,true><<<dim3(TQ/128, 1), 256>>>(ao, wb + W_WO, bo, ob, TQ, CDIM, CDIM, nullptr);
    // 5. masked scatter-mean + residual
    clear_kernel<<<(NPTS*CDIM + 255)/256, 256>>>(sums, cnt);
    scatter_kernel<<<(TQ*CDIM/2 + 255)/256, 256>>>(q_ind, q_mask, ob, sums, cnt);
    resid_kernel<<<(NPTS*CDIM + 255)/256, 256>>>(features, sums, cnt, yb);
    // 6. FFN with pre-norm + residual
    ln_kernel<<<(NPTS*32 + 255)/256, 256>>>(yb, ln2_g, ln2_b, h2b, NPTS);
    gemm_mma<true,false,true><<<dim3((NPTS + 127)/128, FFD/128), 256>>>(h2b, wb + W_FW1, fb1, mid, NPTS, CDIM, FFD, nullptr);
    gemm_mma<false,true,false><<<dim3((NPTS + 127)/128, 1), 256>>>(mid, wb + W_FW2, fb2, out, NPTS, FFD, CDIM, yb);
}